// round 7
// baseline (speedup 1.0000x reference)
#include <cuda_runtime.h>
#include <cuda_bf16.h>
#include <math.h>
#include <stdint.h>

// ---------------------------------------------------------------------------
// MLA forward. Split-bf16 3-term tensor-core GEMMs (Ah.Bh + Ah.Bl + Al.Bh).
// Round 7: GEMM occupancy fix -- 512 threads (4x4 warps, 32x32 warp tile,
// 4 warps/SMSP), 3-stage cp.async ring (one __syncthreads per chunk).
// Causal block skipping on scores / P.V kept from round 6.
// PTX-stable on compute_103 (no tcgen05).
// ---------------------------------------------------------------------------

#define DIM     2048
#define N_HEADS 16
#define Q_LORA  1536
#define KV_LORA 512
#define NOPE    128
#define ROPE    64
#define V_HEAD  128
#define QK_HEAD 192
#define BATCH   2
#define SEQ     2048
#define ROWS    (BATCH * SEQ)
#define QKD     (KV_LORA + ROPE)        // 576
#define SCALE_F 0.0721687836487032f
#define EPS_F   1e-6f

typedef __nv_bfloat16 bf16;

// ------------------------- scratch (device globals) -------------------------
__device__ __align__(256) bf16  g_xh   [(size_t)ROWS * DIM];
__device__ __align__(256) bf16  g_xl   [(size_t)ROWS * DIM];
__device__ __align__(256) bf16  g_wqah [(size_t)Q_LORA * DIM];
__device__ __align__(256) bf16  g_wqal [(size_t)Q_LORA * DIM];
__device__ __align__(256) bf16  g_wqbh [(size_t)N_HEADS * QK_HEAD * Q_LORA];
__device__ __align__(256) bf16  g_wqbl [(size_t)N_HEADS * QK_HEAD * Q_LORA];
__device__ __align__(256) bf16  g_wkvah[(size_t)QKD * DIM];
__device__ __align__(256) bf16  g_wkval[(size_t)QKD * DIM];
__device__ __align__(256) bf16  g_wkvbh[(size_t)N_HEADS * 256 * KV_LORA];
__device__ __align__(256) bf16  g_wkvbl[(size_t)N_HEADS * 256 * KV_LORA];
__device__ __align__(256) bf16  g_woh  [(size_t)DIM * DIM];
__device__ __align__(256) bf16  g_wol  [(size_t)DIM * DIM];

__device__ __align__(256) float g_qa_f [(size_t)ROWS * Q_LORA];
__device__ __align__(256) bf16  g_qah  [(size_t)ROWS * Q_LORA];
__device__ __align__(256) bf16  g_qal  [(size_t)ROWS * Q_LORA];
__device__ __align__(256) bf16  g_qh   [(size_t)ROWS * N_HEADS * QK_HEAD];
__device__ __align__(256) bf16  g_ql   [(size_t)ROWS * N_HEADS * QK_HEAD];
__device__ __align__(256) float g_kv_f [(size_t)ROWS * QKD];
__device__ __align__(256) bf16  g_kfh  [(size_t)ROWS * QKD];
__device__ __align__(256) bf16  g_kfl  [(size_t)ROWS * QKD];
__device__ __align__(256) bf16  g_vTh  [(size_t)BATCH * KV_LORA * SEQ];
__device__ __align__(256) bf16  g_vTl  [(size_t)BATCH * KV_LORA * SEQ];
__device__ __align__(256) bf16  g_wTh  [(size_t)N_HEADS * KV_LORA * NOPE];
__device__ __align__(256) bf16  g_wTl  [(size_t)N_HEADS * KV_LORA * NOPE];
__device__ __align__(256) bf16  g_qfh  [(size_t)ROWS * N_HEADS * QKD];
__device__ __align__(256) bf16  g_qfl  [(size_t)ROWS * N_HEADS * QKD];
__device__ __align__(256) float g_sc   [(size_t)BATCH * N_HEADS * SEQ * SEQ];
__device__ __align__(256) bf16  g_Ph   [(size_t)BATCH * N_HEADS * SEQ * SEQ];
__device__ __align__(256) bf16  g_Pl   [(size_t)BATCH * N_HEADS * SEQ * SEQ];
__device__ __align__(256) bf16  g_ath  [(size_t)ROWS * N_HEADS * KV_LORA];
__device__ __align__(256) bf16  g_atl  [(size_t)ROWS * N_HEADS * KV_LORA];
__device__ __align__(256) bf16  g_o2h  [(size_t)ROWS * DIM];
__device__ __align__(256) bf16  g_o2l  [(size_t)ROWS * DIM];

// ----------------------------- helpers --------------------------------------
__device__ __forceinline__ uint32_t smem_u32(const void* p) {
    uint32_t a;
    asm("{ .reg .u64 t; cvta.to.shared.u64 t, %1; cvt.u32.u64 %0, t; }"
        : "=r"(a) : "l"(p));
    return a;
}
__device__ __forceinline__ void cp16(uint32_t dst, const void* src) {
    asm volatile("cp.async.ca.shared.global [%0], [%1], 16;"
                 :: "r"(dst), "l"(src) : "memory");
}
#define CP_COMMIT() asm volatile("cp.async.commit_group;" ::: "memory")
#define CP_WAIT(n)  asm volatile("cp.async.wait_group %0;" :: "n"(n) : "memory")

__device__ __forceinline__ void ldm_x4(uint32_t* r, uint32_t addr) {
    asm volatile("ldmatrix.sync.aligned.m8n8.x4.shared.b16 {%0,%1,%2,%3}, [%4];"
                 : "=r"(r[0]), "=r"(r[1]), "=r"(r[2]), "=r"(r[3]) : "r"(addr));
}
__device__ __forceinline__ void mma_bf16(float* d, const uint32_t* a,
                                         const uint32_t* b) {
    asm volatile(
        "mma.sync.aligned.m16n8k16.row.col.f32.bf16.bf16.f32 "
        "{%0,%1,%2,%3}, {%4,%5,%6,%7}, {%8,%9}, {%0,%1,%2,%3};"
        : "+f"(d[0]), "+f"(d[1]), "+f"(d[2]), "+f"(d[3])
        : "r"(a[0]), "r"(a[1]), "r"(a[2]), "r"(a[3]), "r"(b[0]), "r"(b[1]));
}
__device__ __forceinline__ void bsplit(float x, bf16& h, bf16& l) {
    h = __float2bfloat16_rn(x);
    l = __float2bfloat16_rn(x - __bfloat162float(h));
}

// ----------------------- GEMM: C = alpha * A.B^T ----------------------------
// A,B pre-split bf16 hi/lo, K-major. M%128==0, K%32==0, N arbitrary.
// OUTM=0: C f32.  OUTM=1: C split to Ch/Cl bf16.
// mode bit0: skip tiles with n0 > m0 (causal scores)
// mode bit1: limit K to m0+128     (causal P.V)
#define ROWB 80
#define TILE_BYTES (128 * ROWB)          // 10240
#define STAGE_BYTES (4 * TILE_BYTES)     // Ah,Al,Bh,Bl = 40960
#define NSTAGE 3
#define SMEM_BYTES (NSTAGE * STAGE_BYTES) // 122880

// one 128 x 32 bf16 tile; 512 threads -> 1 cp.async each
__device__ __forceinline__ void load_tile_bf(uint32_t dst, const bf16* __restrict__ src,
                                             int ld, int k0, int limit, int tid) {
    const int row = tid >> 2, seg = tid & 3;
    const uint32_t d = dst + (uint32_t)(row * ROWB + seg * 16);
    if (row < limit) {
        cp16(d, src + (size_t)row * ld + k0 + seg * 8);
    } else {
        asm volatile("st.shared.v4.b32 [%0], {%1,%1,%1,%1};"
                     :: "r"(d), "r"(0) : "memory");
    }
}
__device__ __forceinline__ void load_stage(uint32_t base,
                                           const bf16* Ath, const bf16* Atl,
                                           const bf16* Bth, const bf16* Btl,
                                           int lda, int ldb, int k0, int nlim, int tid) {
    load_tile_bf(base + 0 * TILE_BYTES, Ath, lda, k0, 128, tid);
    load_tile_bf(base + 1 * TILE_BYTES, Atl, lda, k0, 128, tid);
    load_tile_bf(base + 2 * TILE_BYTES, Bth, ldb, k0, nlim, tid);
    load_tile_bf(base + 3 * TILE_BYTES, Btl, ldb, k0, nlim, tid);
}

template <int OUTM>
__global__ void __launch_bounds__(512)
gemm_bf3(const bf16* __restrict__ Ah, const bf16* __restrict__ Al,
         const bf16* __restrict__ Bh, const bf16* __restrict__ Bl,
         float* __restrict__ C, bf16* __restrict__ Ch, bf16* __restrict__ Cl,
         int M, int N, int K, int lda, int ldb, int ldc,
         long sAo, long sAi, long sBo, long sBi, long sCo, long sCi,
         int inner, float alpha, int mode)
{
    const int m0 = blockIdx.x * 128, n0 = blockIdx.y * 128;
    if ((mode & 1) && n0 > m0) return;          // causal tile skip

    extern __shared__ char smem[];
    const uint32_t sb = smem_u32(smem);
    const int tid = threadIdx.x, lane = tid & 31, wid = tid >> 5;
    const int wm = wid & 3, wn = wid >> 2;      // 4 x 4 warp grid
    const int g = lane >> 2, tig = lane & 3;

    const int z = blockIdx.z, zo = z / inner, zi = z - zo * inner;
    const long ofAB = (long)zo * sAo + (long)zi * sAi;
    const long ofB  = (long)zo * sBo + (long)zi * sBi;
    const long ofC  = (long)zo * sCo + (long)zi * sCi;
    Ah += ofAB; Al += ofAB;
    Bh += ofB;  Bl += ofB;

    const bf16* Ath = Ah + (size_t)m0 * lda;
    const bf16* Atl = Al + (size_t)m0 * lda;
    const bf16* Bth = Bh + (size_t)n0 * ldb;
    const bf16* Btl = Bl + (size_t)n0 * ldb;
    const int nlim = min(128, N - n0);

    float acc[2][4][4];
#pragma unroll
    for (int i = 0; i < 2; i++)
#pragma unroll
        for (int j = 0; j < 4; j++)
#pragma unroll
            for (int r = 0; r < 4; r++) acc[i][j][r] = 0.f;

    const int Keff = (mode & 2) ? min(K, m0 + 128) : K;
    const int nch = Keff >> 5;

    load_stage(sb, Ath, Atl, Bth, Btl, lda, ldb, 0, nlim, tid);
    CP_COMMIT();
    if (nch > 1)
        load_stage(sb + STAGE_BYTES, Ath, Atl, Bth, Btl, lda, ldb, 32, nlim, tid);
    CP_COMMIT();

    const uint32_t aoffL = (uint32_t)((wm * 32 + (lane & 15)) * ROWB + (lane >> 4) * 16);
    const uint32_t boffL = (uint32_t)((wn * 32 + ((lane >> 4) & 1) * 8 + (lane & 7)) * ROWB
                                      + ((lane >> 3) & 1) * 16);

    int stage = 0;
    for (int c = 0; c < nch; c++) {
        if (c + 1 < nch) { CP_WAIT(1); } else { CP_WAIT(0); }
        __syncthreads();

        if (c + 2 < nch) {
            int ns = stage + 2; if (ns >= NSTAGE) ns -= NSTAGE;
            load_stage(sb + ns * STAGE_BYTES, Ath, Atl, Bth, Btl,
                       lda, ldb, (c + 2) << 5, nlim, tid);
            CP_COMMIT();
        } else {
            CP_COMMIT();    // keep group accounting uniform
        }

        const uint32_t base = sb + stage * STAGE_BYTES;
        const uint32_t aA = base + aoffL;
        const uint32_t bA = base + 2 * TILE_BYTES + boffL;

#pragma unroll
        for (int ks = 0; ks < 2; ks++) {
            uint32_t ah[2][4], al[2][4], bh[2][4], bl[2][4];
#pragma unroll
            for (int i = 0; i < 2; i++) {
                ldm_x4(ah[i], aA + ks * 32 + i * 16 * ROWB);
                ldm_x4(al[i], aA + TILE_BYTES + ks * 32 + i * 16 * ROWB);
            }
#pragma unroll
            for (int jj = 0; jj < 2; jj++) {
                ldm_x4(bh[jj], bA + ks * 32 + jj * 16 * ROWB);
                ldm_x4(bl[jj], bA + TILE_BYTES + ks * 32 + jj * 16 * ROWB);
            }
#pragma unroll
            for (int i = 0; i < 2; i++)
#pragma unroll
                for (int j = 0; j < 4; j++) {
                    const uint32_t* bhp = &bh[j >> 1][(j & 1) * 2];
                    const uint32_t* blp = &bl[j >> 1][(j & 1) * 2];
                    mma_bf16(acc[i][j], al[i], bhp);
                    mma_bf16(acc[i][j], ah[i], blp);
                    mma_bf16(acc[i][j], ah[i], bhp);
                }
        }
        stage = (stage + 1 == NSTAGE) ? 0 : stage + 1;
    }

    // epilogue
#pragma unroll
    for (int i = 0; i < 2; i++) {
        const int r0 = m0 + wm * 32 + i * 16 + g;
#pragma unroll
        for (int j = 0; j < 4; j++) {
            const int col = n0 + wn * 32 + j * 8 + tig * 2;
            if (col >= N) continue;
            const float c0 = alpha * acc[i][j][0], c1 = alpha * acc[i][j][1];
            const float c2 = alpha * acc[i][j][2], c3 = alpha * acc[i][j][3];
            if (OUTM == 0) {
                float* p0 = C + ofC + (size_t)r0 * ldc + col;
                float* p1 = C + ofC + (size_t)(r0 + 8) * ldc + col;
                if (col + 1 < N) {
                    *reinterpret_cast<float2*>(p0) = make_float2(c0, c1);
                    *reinterpret_cast<float2*>(p1) = make_float2(c2, c3);
                } else { p0[0] = c0; p1[0] = c2; }
            } else {
                bf16 h0, l0, h1, l1, h2, l2, h3, l3;
                bsplit(c0, h0, l0); bsplit(c1, h1, l1);
                bsplit(c2, h2, l2); bsplit(c3, h3, l3);
                *reinterpret_cast<__nv_bfloat162*>(Ch + ofC + (size_t)r0 * ldc + col)
                    = __nv_bfloat162(h0, h1);
                *reinterpret_cast<__nv_bfloat162*>(Cl + ofC + (size_t)r0 * ldc + col)
                    = __nv_bfloat162(l0, l1);
                *reinterpret_cast<__nv_bfloat162*>(Ch + ofC + (size_t)(r0 + 8) * ldc + col)
                    = __nv_bfloat162(h2, h3);
                *reinterpret_cast<__nv_bfloat162*>(Cl + ofC + (size_t)(r0 + 8) * ldc + col)
                    = __nv_bfloat162(l2, l3);
            }
        }
    }
}

// ---------------------- elementwise split f32 -> bf16 hi/lo ------------------
__global__ void __launch_bounds__(256)
split_kernel(const float* __restrict__ src, bf16* __restrict__ h,
             bf16* __restrict__ l, long n4)
{
    const long stride = (long)gridDim.x * blockDim.x;
    for (long i = blockIdx.x * (long)blockDim.x + threadIdx.x; i < n4; i += stride) {
        const float4 v = reinterpret_cast<const float4*>(src)[i];
        bf16 h0, l0, h1, l1, h2, l2, h3, l3;
        bsplit(v.x, h0, l0); bsplit(v.y, h1, l1);
        bsplit(v.z, h2, l2); bsplit(v.w, h3, l3);
        reinterpret_cast<__nv_bfloat162*>(h)[i * 2]     = __nv_bfloat162(h0, h1);
        reinterpret_cast<__nv_bfloat162*>(h)[i * 2 + 1] = __nv_bfloat162(h2, h3);
        reinterpret_cast<__nv_bfloat162*>(l)[i * 2]     = __nv_bfloat162(l0, l1);
        reinterpret_cast<__nv_bfloat162*>(l)[i * 2 + 1] = __nv_bfloat162(l2, l3);
    }
}

// ------------------- dual bf16 transpose (32x32 tiles) ----------------------
__global__ void __launch_bounds__(256)
transpose_bf2(const bf16* __restrict__ sh, const bf16* __restrict__ sl,
              bf16* __restrict__ dh, bf16* __restrict__ dl,
              int lds, int ldd, long sS, long sD)
{
    __shared__ float th[32][33], tl[32][33];
    const int z = blockIdx.z;
    sh += (long)z * sS; sl += (long)z * sS;
    dh += (long)z * sD; dl += (long)z * sD;
    const int r0 = blockIdx.x * 32, c0 = blockIdx.y * 32;
    const int tx = threadIdx.x, ty = threadIdx.y;
#pragma unroll
    for (int i = 0; i < 4; i++) {
        const long s = (long)(r0 + ty + 8 * i) * lds + c0 + tx;
        th[ty + 8 * i][tx] = __bfloat162float(sh[s]);
        tl[ty + 8 * i][tx] = __bfloat162float(sl[s]);
    }
    __syncthreads();
#pragma unroll
    for (int i = 0; i < 4; i++) {
        const long d = (long)(c0 + ty + 8 * i) * ldd + r0 + tx;
        dh[d] = __float2bfloat16_rn(th[tx][ty + 8 * i]);
        dl[d] = __float2bfloat16_rn(tl[tx][ty + 8 * i]);
    }
}

// --------------------------- rmsnorm: f32 -> split --------------------------
__global__ void __launch_bounds__(256)
rmsnorm_qa_kernel(const float* __restrict__ w)
{
    const long row = blockIdx.x;
    const float* p = g_qa_f + row * Q_LORA;
    const int tid = threadIdx.x;
    float v[6];
    float ss = 0.f;
#pragma unroll
    for (int i = 0; i < 6; i++) { v[i] = p[tid + i * 256]; ss += v[i] * v[i]; }
    __shared__ float red[256];
    red[tid] = ss; __syncthreads();
    for (int o = 128; o > 0; o >>= 1) {
        if (tid < o) red[tid] += red[tid + o];
        __syncthreads();
    }
    const float scale = rsqrtf(red[0] / (float)Q_LORA + EPS_F);
#pragma unroll
    for (int i = 0; i < 6; i++) {
        const int c = tid + i * 256;
        bf16 h, l;
        bsplit(v[i] * scale * w[c], h, l);
        g_qah[row * Q_LORA + c] = h;
        g_qal[row * Q_LORA + c] = l;
    }
}

// ------------- kv_process: f32 kv -> split kf (norm + rope) -----------------
__global__ void __launch_bounds__(256)
kv_process_kernel(const float* __restrict__ kv_norm_w,
                  const float* __restrict__ fcos,
                  const float* __restrict__ fsin)
{
    const long row = blockIdx.x;
    const int pos = (int)(row & (SEQ - 1));
    const float* src = g_kv_f + row * QKD;
    const int tid = threadIdx.x;

    const float v0 = src[tid], v1 = src[tid + 256];
    __shared__ float red[256];
    red[tid] = v0 * v0 + v1 * v1; __syncthreads();
    for (int o = 128; o > 0; o >>= 1) {
        if (tid < o) red[tid] += red[tid + o];
        __syncthreads();
    }
    const float scale = rsqrtf(red[0] / (float)KV_LORA + EPS_F);
    bf16 h, l;
    bsplit(v0 * scale * kv_norm_w[tid], h, l);
    g_kfh[row * QKD + tid] = h; g_kfl[row * QKD + tid] = l;
    bsplit(v1 * scale * kv_norm_w[tid + 256], h, l);
    g_kfh[row * QKD + tid + 256] = h; g_kfl[row * QKD + tid + 256] = l;

    if (tid < 32) {
        const float x0 = src[KV_LORA + 2 * tid];
        const float x1 = src[KV_LORA + 2 * tid + 1];
        const float c = fcos[pos * 32 + tid];
        const float s = fsin[pos * 32 + tid];
        bsplit(x0 * c - x1 * s, h, l);
        g_kfh[row * QKD + KV_LORA + 2 * tid] = h;
        g_kfl[row * QKD + KV_LORA + 2 * tid] = l;
        bsplit(x0 * s + x1 * c, h, l);
        g_kfh[row * QKD + KV_LORA + 2 * tid + 1] = h;
        g_kfl[row * QKD + KV_LORA + 2 * tid + 1] = l;
    }
}

// ------------- q rope -------------------------------------------------------
__global__ void __launch_bounds__(512)
q_process_kernel(const float* __restrict__ fcos, const float* __restrict__ fsin)
{
    const long row = blockIdx.x;
    const int pos = (int)(row & (SEQ - 1));
    const int h = threadIdx.x / 32;
    const int i = threadIdx.x % 32;

    const long si = row * (N_HEADS * QK_HEAD) + h * QK_HEAD + NOPE + 2 * i;
    const float x0 = __bfloat162float(g_qh[si])     + __bfloat162float(g_ql[si]);
    const float x1 = __bfloat162float(g_qh[si + 1]) + __bfloat162float(g_ql[si + 1]);
    const float c = fcos[pos * 32 + i];
    const float s = fsin[pos * 32 + i];
    const long di = row * (N_HEADS * QKD) + h * QKD + KV_LORA + 2 * i;
    bf16 hh, ll;
    bsplit(x0 * c - x1 * s, hh, ll);
    g_qfh[di] = hh; g_qfl[di] = ll;
    bsplit(x0 * s + x1 * c, hh, ll);
    g_qfh[di + 1] = hh; g_qfl[di + 1] = ll;
}

// ------------- softmax (causal extent only) ---------------------------------
__global__ void __launch_bounds__(256)
softmax_mask_kernel(const float* __restrict__ mask)
{
    const long row = blockIdx.x;
    const int s = (int)(row & (SEQ - 1));
    const int T = ((s >> 7) + 1) << 7;
    const float* p = g_sc + row * SEQ;
    const float* mrow = mask + (long)s * SEQ;
    const int tid = threadIdx.x;
    const int t0 = tid * 8;
    const bool act = t0 < T;

    float v[8];
    float mx = -INFINITY;
    if (act) {
        const float4 a = reinterpret_cast<const float4*>(p + t0)[0];
        const float4 b = reinterpret_cast<const float4*>(p + t0)[1];
        const float4 ma = reinterpret_cast<const float4*>(mrow + t0)[0];
        const float4 mb = reinterpret_cast<const float4*>(mrow + t0)[1];
        v[0] = a.x + ma.x; v[1] = a.y + ma.y; v[2] = a.z + ma.z; v[3] = a.w + ma.w;
        v[4] = b.x + mb.x; v[5] = b.y + mb.y; v[6] = b.z + mb.z; v[7] = b.w + mb.w;
#pragma unroll
        for (int i = 0; i < 8; i++) mx = fmaxf(mx, v[i]);
    }
    __shared__ float red[256];
    red[tid] = mx; __syncthreads();
    for (int o = 128; o > 0; o >>= 1) {
        if (tid < o) red[tid] = fmaxf(red[tid], red[tid + o]);
        __syncthreads();
    }
    mx = red[0]; __syncthreads();

    float sum = 0.f;
    if (act) {
#pragma unroll
        for (int i = 0; i < 8; i++) { v[i] = expf(v[i] - mx); sum += v[i]; }
    }
    red[tid] = sum; __syncthreads();
    for (int o = 128; o > 0; o >>= 1) {
        if (tid < o) red[tid] += red[tid + o];
        __syncthreads();
    }
    const float inv = 1.f / red[0];

    if (act) {
#pragma unroll
        for (int i = 0; i < 4; i++) {
            bf16 h0, l0, h1, l1;
            bsplit(v[2 * i] * inv, h0, l0);
            bsplit(v[2 * i + 1] * inv, h1, l1);
            reinterpret_cast<__nv_bfloat162*>(g_Ph + row * SEQ + t0)[i]
                = __nv_bfloat162(h0, h1);
            reinterpret_cast<__nv_bfloat162*>(g_Pl + row * SEQ + t0)[i]
                = __nv_bfloat162(l0, l1);
        }
    }
}

// ---------------------------------------------------------------------------
extern "C" void kernel_launch(void* const* d_in, const int* in_sizes, int n_in,
                              void* d_out, int out_size)
{
    const float* x         = (const float*)d_in[0];
    const float* fcos      = (const float*)d_in[1];
    const float* fsin      = (const float*)d_in[2];
    const float* mask      = (const float*)d_in[3];
    const float* wq_a      = (const float*)d_in[4];
    const float* q_norm_w  = (const float*)d_in[5];
    const float* wq_b      = (const float*)d_in[6];
    const float* wkv_a     = (const float*)d_in[7];
    const float* kv_norm_w = (const float*)d_in[8];
    const float* wkv_b     = (const float*)d_in[9];
    const float* wo        = (const float*)d_in[10];
    float* out = (float*)d_out;

    bf16 *xh, *xl, *wqah, *wqal, *wqbh, *wqbl, *wkvah, *wkval, *wkvbh, *wkvbl;
    bf16 *woh, *wol, *qah, *qal, *qh, *ql, *kfh, *kfl, *vTh, *vTl, *wTh, *wTl;
    bf16 *qfh, *qfl, *Ph, *Pl, *ath, *atl, *o2h, *o2l;
    float *qaf, *kvf, *sc;
    cudaGetSymbolAddress((void**)&xh, g_xh);     cudaGetSymbolAddress((void**)&xl, g_xl);
    cudaGetSymbolAddress((void**)&wqah, g_wqah); cudaGetSymbolAddress((void**)&wqal, g_wqal);
    cudaGetSymbolAddress((void**)&wqbh, g_wqbh); cudaGetSymbolAddress((void**)&wqbl, g_wqbl);
    cudaGetSymbolAddress((void**)&wkvah, g_wkvah); cudaGetSymbolAddress((void**)&wkval, g_wkval);
    cudaGetSymbolAddress((void**)&wkvbh, g_wkvbh); cudaGetSymbolAddress((void**)&wkvbl, g_wkvbl);
    cudaGetSymbolAddress((void**)&woh, g_woh);   cudaGetSymbolAddress((void**)&wol, g_wol);
    cudaGetSymbolAddress((void**)&qaf, g_qa_f);
    cudaGetSymbolAddress((void**)&qah, g_qah);   cudaGetSymbolAddress((void**)&qal, g_qal);
    cudaGetSymbolAddress((void**)&qh, g_qh);     cudaGetSymbolAddress((void**)&ql, g_ql);
    cudaGetSymbolAddress((void**)&kvf, g_kv_f);
    cudaGetSymbolAddress((void**)&kfh, g_kfh);   cudaGetSymbolAddress((void**)&kfl, g_kfl);
    cudaGetSymbolAddress((void**)&vTh, g_vTh);   cudaGetSymbolAddress((void**)&vTl, g_vTl);
    cudaGetSymbolAddress((void**)&wTh, g_wTh);   cudaGetSymbolAddress((void**)&wTl, g_wTl);
    cudaGetSymbolAddress((void**)&qfh, g_qfh);   cudaGetSymbolAddress((void**)&qfl, g_qfl);
    cudaGetSymbolAddress((void**)&sc, g_sc);
    cudaGetSymbolAddress((void**)&Ph, g_Ph);     cudaGetSymbolAddress((void**)&Pl, g_Pl);
    cudaGetSymbolAddress((void**)&ath, g_ath);   cudaGetSymbolAddress((void**)&atl, g_atl);
    cudaGetSymbolAddress((void**)&o2h, g_o2h);   cudaGetSymbolAddress((void**)&o2l, g_o2l);

    cudaFuncSetAttribute(gemm_bf3<0>, cudaFuncAttributeMaxDynamicSharedMemorySize, SMEM_BYTES);
    cudaFuncSetAttribute(gemm_bf3<1>, cudaFuncAttributeMaxDynamicSharedMemorySize, SMEM_BYTES);

    dim3 blk(256);
    dim3 gblk(512);
    dim3 tb(32, 8);

    // 0. split inputs + weights
    auto splits = [&](const float* s, bf16* h, bf16* l, long n) {
        const long n4 = n / 4;
        int gs = (int)min((n4 + 255) / 256, (long)4096);
        split_kernel<<<gs, blk>>>(s, h, l, n4);
    };
    splits(x,     xh,    xl,    (long)ROWS * DIM);
    splits(wq_a,  wqah,  wqal,  (long)Q_LORA * DIM);
    splits(wq_b,  wqbh,  wqbl,  (long)N_HEADS * QK_HEAD * Q_LORA);
    splits(wkv_a, wkvah, wkval, (long)QKD * DIM);
    splits(wkv_b, wkvbh, wkvbl, (long)N_HEADS * 256 * KV_LORA);
    splits(wo,    woh,   wol,   (long)DIM * DIM);

    // 1. qa_f = x @ wq_a^T  (f32 out)
    gemm_bf3<0><<<dim3(ROWS/128, Q_LORA/128, 1), gblk, SMEM_BYTES>>>(
        xh, xl, wqah, wqal, qaf, nullptr, nullptr,
        ROWS, Q_LORA, DIM, DIM, DIM, Q_LORA, 0,0, 0,0, 0,0, 1, 1.f, 0);

    // 2. rmsnorm -> split qa
    rmsnorm_qa_kernel<<<ROWS, blk>>>(q_norm_w);

    // 3. q = qa @ wq_b^T  (split out)
    gemm_bf3<1><<<dim3(ROWS/128, (N_HEADS*QK_HEAD)/128, 1), gblk, SMEM_BYTES>>>(
        qah, qal, wqbh, wqbl, nullptr, qh, ql,
        ROWS, N_HEADS*QK_HEAD, Q_LORA, Q_LORA, Q_LORA, N_HEADS*QK_HEAD,
        0,0, 0,0, 0,0, 1, 1.f, 0);

    // 4. kv_f = x @ wkv_a^T  (f32 out)
    gemm_bf3<0><<<dim3(ROWS/128, (QKD+127)/128, 1), gblk, SMEM_BYTES>>>(
        xh, xl, wkvah, wkval, kvf, nullptr, nullptr,
        ROWS, QKD, DIM, DIM, DIM, QKD, 0,0, 0,0, 0,0, 1, 1.f, 0);

    // 5. kv -> split kf
    kv_process_kernel<<<ROWS, blk>>>(kv_norm_w, fcos, fsin);

    // 6. rope(q_pe) -> qf
    q_process_kernel<<<ROWS, 512>>>(fcos, fsin);

    // 6b/6c. transposes
    transpose_bf2<<<dim3(SEQ/32, KV_LORA/32, BATCH), tb>>>(
        kfh, kfl, vTh, vTl, QKD, SEQ, (long)SEQ*QKD, (long)KV_LORA*SEQ);
    transpose_bf2<<<dim3(NOPE/32, KV_LORA/32, N_HEADS), tb>>>(
        wkvbh, wkvbl, wTh, wTl, KV_LORA, NOPE, (long)256*KV_LORA, (long)KV_LORA*NOPE);

    // 7. qf[:,:,0:512] = q_nope @ wT[h]^T  (batched h)
    gemm_bf3<1><<<dim3(ROWS/128, KV_LORA/128, N_HEADS), gblk, SMEM_BYTES>>>(
        qh, ql, wTh, wTl, nullptr, qfh, qfl,
        ROWS, KV_LORA, NOPE, N_HEADS*QK_HEAD, NOPE, N_HEADS*QKD,
        0, QK_HEAD, 0, (long)KV_LORA*NOPE, 0, QKD, N_HEADS, 1.f, 0);

    // 8. scores = SCALE * qf @ kf^T  (causal tiles only)
    gemm_bf3<0><<<dim3(SEQ/128, SEQ/128, BATCH*N_HEADS), gblk, SMEM_BYTES>>>(
        qfh, qfl, kfh, kfl, sc, nullptr, nullptr,
        SEQ, SEQ, QKD, N_HEADS*QKD, QKD, SEQ,
        (long)SEQ*N_HEADS*QKD, QKD,
        (long)SEQ*QKD, 0,
        (long)N_HEADS*SEQ*SEQ, (long)SEQ*SEQ,
        N_HEADS, SCALE_F, 1);

    // 9. softmax -> split P (causal extent)
    softmax_mask_kernel<<<BATCH*N_HEADS*SEQ, blk>>>(mask);

    // 10. attno = P @ vT^T  (causal K bound)
    gemm_bf3<1><<<dim3(SEQ/128, KV_LORA/128, BATCH*N_HEADS), gblk, SMEM_BYTES>>>(
        Ph, Pl, vTh, vTl, nullptr, ath, atl,
        SEQ, KV_LORA, SEQ, SEQ, SEQ, N_HEADS*KV_LORA,
        (long)N_HEADS*SEQ*SEQ, (long)SEQ*SEQ,
        (long)KV_LORA*SEQ, 0,
        (long)SEQ*N_HEADS*KV_LORA, KV_LORA,
        N_HEADS, 1.f, 2);

    // 11. o2 = attno @ wkvb_v^T  (batched h)
    gemm_bf3<1><<<dim3(ROWS/128, V_HEAD/128, N_HEADS), gblk, SMEM_BYTES>>>(
        ath, atl, wkvbh + (size_t)NOPE*KV_LORA, wkvbl + (size_t)NOPE*KV_LORA,
        nullptr, o2h, o2l,
        ROWS, V_HEAD, KV_LORA, N_HEADS*KV_LORA, KV_LORA, DIM,
        0, KV_LORA, 0, (long)256*KV_LORA, 0, V_HEAD, N_HEADS, 1.f, 0);

    // 12. out = o2 @ wo^T  (f32 out)
    gemm_bf3<0><<<dim3(ROWS/128, DIM/128, 1), gblk, SMEM_BYTES>>>(
        o2h, o2l, woh, wol, out, nullptr, nullptr,
        ROWS, DIM, DIM, DIM, DIM, DIM, 0,0, 0,0, 0,0, 1, 1.f, 0);
}

// round 8
// speedup vs baseline: 1.0084x; 1.0084x over previous
#include <cuda_runtime.h>
#include <cuda_bf16.h>
#include <math.h>
#include <stdint.h>

// ---------------------------------------------------------------------------
// MLA forward. Split-bf16 3-term tensor-core GEMMs (Ah.Bh + Ah.Bl + Al.Bh).
// Round 8: CTA tile 256x128, 512 threads, 4x4 warp grid, warp tile 64x32
// (keeps the 1:4 ldmatrix:MMA ratio of round 6 -- round 7 showed the smem
// crossbar is the binding resource), 3-stage cp.async ring, 4 warps/SMSP.
// Causal block skipping retained. PTX-stable on compute_103 (no tcgen05).
// ---------------------------------------------------------------------------

#define DIM     2048
#define N_HEADS 16
#define Q_LORA  1536
#define KV_LORA 512
#define NOPE    128
#define ROPE    64
#define V_HEAD  128
#define QK_HEAD 192
#define BATCH   2
#define SEQ     2048
#define ROWS    (BATCH * SEQ)
#define QKD     (KV_LORA + ROPE)        // 576
#define SCALE_F 0.0721687836487032f
#define EPS_F   1e-6f

typedef __nv_bfloat16 bf16;

// ------------------------- scratch (device globals) -------------------------
__device__ __align__(256) bf16  g_xh   [(size_t)ROWS * DIM];
__device__ __align__(256) bf16  g_xl   [(size_t)ROWS * DIM];
__device__ __align__(256) bf16  g_wqah [(size_t)Q_LORA * DIM];
__device__ __align__(256) bf16  g_wqal [(size_t)Q_LORA * DIM];
__device__ __align__(256) bf16  g_wqbh [(size_t)N_HEADS * QK_HEAD * Q_LORA];
__device__ __align__(256) bf16  g_wqbl [(size_t)N_HEADS * QK_HEAD * Q_LORA];
__device__ __align__(256) bf16  g_wkvah[(size_t)QKD * DIM];
__device__ __align__(256) bf16  g_wkval[(size_t)QKD * DIM];
__device__ __align__(256) bf16  g_wkvbh[(size_t)N_HEADS * 256 * KV_LORA];
__device__ __align__(256) bf16  g_wkvbl[(size_t)N_HEADS * 256 * KV_LORA];
__device__ __align__(256) bf16  g_woh  [(size_t)DIM * DIM];
__device__ __align__(256) bf16  g_wol  [(size_t)DIM * DIM];

__device__ __align__(256) float g_qa_f [(size_t)ROWS * Q_LORA];
__device__ __align__(256) bf16  g_qah  [(size_t)ROWS * Q_LORA];
__device__ __align__(256) bf16  g_qal  [(size_t)ROWS * Q_LORA];
__device__ __align__(256) bf16  g_qh   [(size_t)ROWS * N_HEADS * QK_HEAD];
__device__ __align__(256) bf16  g_ql   [(size_t)ROWS * N_HEADS * QK_HEAD];
__device__ __align__(256) float g_kv_f [(size_t)ROWS * QKD];
__device__ __align__(256) bf16  g_kfh  [(size_t)ROWS * QKD];
__device__ __align__(256) bf16  g_kfl  [(size_t)ROWS * QKD];
__device__ __align__(256) bf16  g_vTh  [(size_t)BATCH * KV_LORA * SEQ];
__device__ __align__(256) bf16  g_vTl  [(size_t)BATCH * KV_LORA * SEQ];
__device__ __align__(256) bf16  g_wTh  [(size_t)N_HEADS * KV_LORA * NOPE];
__device__ __align__(256) bf16  g_wTl  [(size_t)N_HEADS * KV_LORA * NOPE];
__device__ __align__(256) bf16  g_qfh  [(size_t)ROWS * N_HEADS * QKD];
__device__ __align__(256) bf16  g_qfl  [(size_t)ROWS * N_HEADS * QKD];
__device__ __align__(256) float g_sc   [(size_t)BATCH * N_HEADS * SEQ * SEQ];
__device__ __align__(256) bf16  g_Ph   [(size_t)BATCH * N_HEADS * SEQ * SEQ];
__device__ __align__(256) bf16  g_Pl   [(size_t)BATCH * N_HEADS * SEQ * SEQ];
__device__ __align__(256) bf16  g_ath  [(size_t)ROWS * N_HEADS * KV_LORA];
__device__ __align__(256) bf16  g_atl  [(size_t)ROWS * N_HEADS * KV_LORA];
__device__ __align__(256) bf16  g_o2h  [(size_t)ROWS * DIM];
__device__ __align__(256) bf16  g_o2l  [(size_t)ROWS * DIM];

// ----------------------------- helpers --------------------------------------
__device__ __forceinline__ uint32_t smem_u32(const void* p) {
    uint32_t a;
    asm("{ .reg .u64 t; cvta.to.shared.u64 t, %1; cvt.u32.u64 %0, t; }"
        : "=r"(a) : "l"(p));
    return a;
}
__device__ __forceinline__ void cp16(uint32_t dst, const void* src) {
    asm volatile("cp.async.ca.shared.global [%0], [%1], 16;"
                 :: "r"(dst), "l"(src) : "memory");
}
#define CP_COMMIT() asm volatile("cp.async.commit_group;" ::: "memory")
#define CP_WAIT(n)  asm volatile("cp.async.wait_group %0;" :: "n"(n) : "memory")

__device__ __forceinline__ void ldm_x4(uint32_t* r, uint32_t addr) {
    asm volatile("ldmatrix.sync.aligned.m8n8.x4.shared.b16 {%0,%1,%2,%3}, [%4];"
                 : "=r"(r[0]), "=r"(r[1]), "=r"(r[2]), "=r"(r[3]) : "r"(addr));
}
__device__ __forceinline__ void mma_bf16(float* d, const uint32_t* a,
                                         const uint32_t* b) {
    asm volatile(
        "mma.sync.aligned.m16n8k16.row.col.f32.bf16.bf16.f32 "
        "{%0,%1,%2,%3}, {%4,%5,%6,%7}, {%8,%9}, {%0,%1,%2,%3};"
        : "+f"(d[0]), "+f"(d[1]), "+f"(d[2]), "+f"(d[3])
        : "r"(a[0]), "r"(a[1]), "r"(a[2]), "r"(a[3]), "r"(b[0]), "r"(b[1]));
}
__device__ __forceinline__ void bsplit(float x, bf16& h, bf16& l) {
    h = __float2bfloat16_rn(x);
    l = __float2bfloat16_rn(x - __bfloat162float(h));
}

// ----------------------- GEMM: C = alpha * A.B^T ----------------------------
// CTA tile 256x128, BK=32. A,B pre-split bf16 hi/lo, K-major.
// M%256==0, K%32==0, N arbitrary.
// OUTM=0: C f32.  OUTM=1: C split to Ch/Cl bf16.
// mode bit0: skip tiles with n0 > m0+128 (causal scores)
// mode bit1: limit K to m0+256        (causal P.V)
#define ROWB 80
#define AT_B (256 * ROWB)                // 20480
#define BT_B (128 * ROWB)                // 10240
#define STG_B (2 * AT_B + 2 * BT_B)      // 61440: [Ah][Al][Bh][Bl]
#define NSTAGE 3
#define SMEM_BYTES (NSTAGE * STG_B)      // 184320

__device__ __forceinline__ void load_tileA(uint32_t dst, const bf16* __restrict__ src,
                                           int ld, int k0, int tid) {
#pragma unroll
    for (int it = 0; it < 2; it++) {
        const int idx = tid + it * 512;
        const int row = idx >> 2, seg = idx & 3;
        cp16(dst + (uint32_t)(row * ROWB + seg * 16),
             src + (size_t)row * ld + k0 + seg * 8);
    }
}
__device__ __forceinline__ void load_tileB(uint32_t dst, const bf16* __restrict__ src,
                                           int ld, int k0, int limit, int tid) {
    const int row = tid >> 2, seg = tid & 3;
    const uint32_t d = dst + (uint32_t)(row * ROWB + seg * 16);
    if (row < limit) {
        cp16(d, src + (size_t)row * ld + k0 + seg * 8);
    } else {
        asm volatile("st.shared.v4.b32 [%0], {%1,%1,%1,%1};"
                     :: "r"(d), "r"(0) : "memory");
    }
}
__device__ __forceinline__ void load_stage(uint32_t base,
                                           const bf16* Ath, const bf16* Atl,
                                           const bf16* Bth, const bf16* Btl,
                                           int lda, int ldb, int k0, int nlim, int tid) {
    load_tileA(base,                Ath, lda, k0, tid);
    load_tileA(base + AT_B,         Atl, lda, k0, tid);
    load_tileB(base + 2 * AT_B,        Bth, ldb, k0, nlim, tid);
    load_tileB(base + 2 * AT_B + BT_B, Btl, ldb, k0, nlim, tid);
}

template <int OUTM>
__global__ void __launch_bounds__(512)
gemm_bf3(const bf16* __restrict__ Ah, const bf16* __restrict__ Al,
         const bf16* __restrict__ Bh, const bf16* __restrict__ Bl,
         float* __restrict__ C, bf16* __restrict__ Ch, bf16* __restrict__ Cl,
         int M, int N, int K, int lda, int ldb, int ldc,
         long sAo, long sAi, long sBo, long sBi, long sCo, long sCi,
         int inner, float alpha, int mode)
{
    const int m0 = blockIdx.x * 256, n0 = blockIdx.y * 128;
    if ((mode & 1) && n0 > m0 + 128) return;    // causal tile skip

    extern __shared__ char smem[];
    const uint32_t sb = smem_u32(smem);
    const int tid = threadIdx.x, lane = tid & 31, wid = tid >> 5;
    const int wm = wid & 3, wn = wid >> 2;      // 4(m) x 4(n) warps
    const int g = lane >> 2, tig = lane & 3;

    const int z = blockIdx.z, zo = z / inner, zi = z - zo * inner;
    const long ofAB = (long)zo * sAo + (long)zi * sAi;
    const long ofB  = (long)zo * sBo + (long)zi * sBi;
    const long ofC  = (long)zo * sCo + (long)zi * sCi;
    Ah += ofAB; Al += ofAB;
    Bh += ofB;  Bl += ofB;

    const bf16* Ath = Ah + (size_t)m0 * lda;
    const bf16* Atl = Al + (size_t)m0 * lda;
    const bf16* Bth = Bh + (size_t)n0 * ldb;
    const bf16* Btl = Bl + (size_t)n0 * ldb;
    const int nlim = min(128, N - n0);

    float acc[4][4][4];
#pragma unroll
    for (int i = 0; i < 4; i++)
#pragma unroll
        for (int j = 0; j < 4; j++)
#pragma unroll
            for (int r = 0; r < 4; r++) acc[i][j][r] = 0.f;

    const int Keff = (mode & 2) ? min(K, m0 + 256) : K;
    const int nch = Keff >> 5;

    load_stage(sb, Ath, Atl, Bth, Btl, lda, ldb, 0, nlim, tid);
    CP_COMMIT();
    if (nch > 1)
        load_stage(sb + STG_B, Ath, Atl, Bth, Btl, lda, ldb, 32, nlim, tid);
    CP_COMMIT();

    // warp tile 64x32: rows wm*64..+63, cols wn*32..+31
    const uint32_t aoffL = (uint32_t)((wm * 64 + (lane & 15)) * ROWB + (lane >> 4) * 16);
    const uint32_t boffL = (uint32_t)((wn * 32 + ((lane >> 4) & 1) * 8 + (lane & 7)) * ROWB
                                      + ((lane >> 3) & 1) * 16);

    int stage = 0;
    for (int c = 0; c < nch; c++) {
        if (c + 1 < nch) { CP_WAIT(1); } else { CP_WAIT(0); }
        __syncthreads();

        if (c + 2 < nch) {
            int ns = stage + 2; if (ns >= NSTAGE) ns -= NSTAGE;
            load_stage(sb + ns * STG_B, Ath, Atl, Bth, Btl,
                       lda, ldb, (c + 2) << 5, nlim, tid);
            CP_COMMIT();
        } else {
            CP_COMMIT();
        }

        const uint32_t base = sb + stage * STG_B;
        const uint32_t aA = base + aoffL;
        const uint32_t bA = base + 2 * AT_B + boffL;

#pragma unroll
        for (int ks = 0; ks < 2; ks++) {
            uint32_t bh[2][4], bl[2][4];
#pragma unroll
            for (int jj = 0; jj < 2; jj++) {
                ldm_x4(bh[jj], bA + ks * 32 + jj * 16 * ROWB);
                ldm_x4(bl[jj], bA + BT_B + ks * 32 + jj * 16 * ROWB);
            }
#pragma unroll
            for (int i = 0; i < 4; i++) {
                uint32_t ahf[4], alf[4];
                ldm_x4(ahf, aA + ks * 32 + i * 16 * ROWB);
                ldm_x4(alf, aA + AT_B + ks * 32 + i * 16 * ROWB);
#pragma unroll
                for (int j = 0; j < 4; j++) {
                    const uint32_t* bhp = &bh[j >> 1][(j & 1) * 2];
                    const uint32_t* blp = &bl[j >> 1][(j & 1) * 2];
                    mma_bf16(acc[i][j], alf, bhp);
                    mma_bf16(acc[i][j], ahf, blp);
                    mma_bf16(acc[i][j], ahf, bhp);
                }
            }
        }
        stage = (stage + 1 == NSTAGE) ? 0 : stage + 1;
    }

    // epilogue
#pragma unroll
    for (int i = 0; i < 4; i++) {
        const int r0 = m0 + wm * 64 + i * 16 + g;
#pragma unroll
        for (int j = 0; j < 4; j++) {
            const int col = n0 + wn * 32 + j * 8 + tig * 2;
            if (col >= N) continue;
            const float c0 = alpha * acc[i][j][0], c1 = alpha * acc[i][j][1];
            const float c2 = alpha * acc[i][j][2], c3 = alpha * acc[i][j][3];
            if (OUTM == 0) {
                float* p0 = C + ofC + (size_t)r0 * ldc + col;
                float* p1 = C + ofC + (size_t)(r0 + 8) * ldc + col;
                if (col + 1 < N) {
                    *reinterpret_cast<float2*>(p0) = make_float2(c0, c1);
                    *reinterpret_cast<float2*>(p1) = make_float2(c2, c3);
                } else { p0[0] = c0; p1[0] = c2; }
            } else {
                bf16 h0, l0, h1, l1, h2, l2, h3, l3;
                bsplit(c0, h0, l0); bsplit(c1, h1, l1);
                bsplit(c2, h2, l2); bsplit(c3, h3, l3);
                *reinterpret_cast<__nv_bfloat162*>(Ch + ofC + (size_t)r0 * ldc + col)
                    = __nv_bfloat162(h0, h1);
                *reinterpret_cast<__nv_bfloat162*>(Cl + ofC + (size_t)r0 * ldc + col)
                    = __nv_bfloat162(l0, l1);
                *reinterpret_cast<__nv_bfloat162*>(Ch + ofC + (size_t)(r0 + 8) * ldc + col)
                    = __nv_bfloat162(h2, h3);
                *reinterpret_cast<__nv_bfloat162*>(Cl + ofC + (size_t)(r0 + 8) * ldc + col)
                    = __nv_bfloat162(l2, l3);
            }
        }
    }
}

// ---------------------- elementwise split f32 -> bf16 hi/lo ------------------
__global__ void __launch_bounds__(256)
split_kernel(const float* __restrict__ src, bf16* __restrict__ h,
             bf16* __restrict__ l, long n4)
{
    const long stride = (long)gridDim.x * blockDim.x;
    for (long i = blockIdx.x * (long)blockDim.x + threadIdx.x; i < n4; i += stride) {
        const float4 v = reinterpret_cast<const float4*>(src)[i];
        bf16 h0, l0, h1, l1, h2, l2, h3, l3;
        bsplit(v.x, h0, l0); bsplit(v.y, h1, l1);
        bsplit(v.z, h2, l2); bsplit(v.w, h3, l3);
        reinterpret_cast<__nv_bfloat162*>(h)[i * 2]     = __nv_bfloat162(h0, h1);
        reinterpret_cast<__nv_bfloat162*>(h)[i * 2 + 1] = __nv_bfloat162(h2, h3);
        reinterpret_cast<__nv_bfloat162*>(l)[i * 2]     = __nv_bfloat162(l0, l1);
        reinterpret_cast<__nv_bfloat162*>(l)[i * 2 + 1] = __nv_bfloat162(l2, l3);
    }
}

// ------------------- dual bf16 transpose (32x32 tiles) ----------------------
__global__ void __launch_bounds__(256)
transpose_bf2(const bf16* __restrict__ sh, const bf16* __restrict__ sl,
              bf16* __restrict__ dh, bf16* __restrict__ dl,
              int lds, int ldd, long sS, long sD)
{
    __shared__ float th[32][33], tl[32][33];
    const int z = blockIdx.z;
    sh += (long)z * sS; sl += (long)z * sS;
    dh += (long)z * sD; dl += (long)z * sD;
    const int r0 = blockIdx.x * 32, c0 = blockIdx.y * 32;
    const int tx = threadIdx.x, ty = threadIdx.y;
#pragma unroll
    for (int i = 0; i < 4; i++) {
        const long s = (long)(r0 + ty + 8 * i) * lds + c0 + tx;
        th[ty + 8 * i][tx] = __bfloat162float(sh[s]);
        tl[ty + 8 * i][tx] = __bfloat162float(sl[s]);
    }
    __syncthreads();
#pragma unroll
    for (int i = 0; i < 4; i++) {
        const long d = (long)(c0 + ty + 8 * i) * ldd + r0 + tx;
        dh[d] = __float2bfloat16_rn(th[tx][ty + 8 * i]);
        dl[d] = __float2bfloat16_rn(tl[tx][ty + 8 * i]);
    }
}

// --------------------------- rmsnorm: f32 -> split --------------------------
__global__ void __launch_bounds__(256)
rmsnorm_qa_kernel(const float* __restrict__ w)
{
    const long row = blockIdx.x;
    const float* p = g_qa_f + row * Q_LORA;
    const int tid = threadIdx.x;
    float v[6];
    float ss = 0.f;
#pragma unroll
    for (int i = 0; i < 6; i++) { v[i] = p[tid + i * 256]; ss += v[i] * v[i]; }
    __shared__ float red[256];
    red[tid] = ss; __syncthreads();
    for (int o = 128; o > 0; o >>= 1) {
        if (tid < o) red[tid] += red[tid + o];
        __syncthreads();
    }
    const float scale = rsqrtf(red[0] / (float)Q_LORA + EPS_F);
#pragma unroll
    for (int i = 0; i < 6; i++) {
        const int c = tid + i * 256;
        bf16 h, l;
        bsplit(v[i] * scale * w[c], h, l);
        g_qah[row * Q_LORA + c] = h;
        g_qal[row * Q_LORA + c] = l;
    }
}

// ------------- kv_process: f32 kv -> split kf (norm + rope) -----------------
__global__ void __launch_bounds__(256)
kv_process_kernel(const float* __restrict__ kv_norm_w,
                  const float* __restrict__ fcos,
                  const float* __restrict__ fsin)
{
    const long row = blockIdx.x;
    const int pos = (int)(row & (SEQ - 1));
    const float* src = g_kv_f + row * QKD;
    const int tid = threadIdx.x;

    const float v0 = src[tid], v1 = src[tid + 256];
    __shared__ float red[256];
    red[tid] = v0 * v0 + v1 * v1; __syncthreads();
    for (int o = 128; o > 0; o >>= 1) {
        if (tid < o) red[tid] += red[tid + o];
        __syncthreads();
    }
    const float scale = rsqrtf(red[0] / (float)KV_LORA + EPS_F);
    bf16 h, l;
    bsplit(v0 * scale * kv_norm_w[tid], h, l);
    g_kfh[row * QKD + tid] = h; g_kfl[row * QKD + tid] = l;
    bsplit(v1 * scale * kv_norm_w[tid + 256], h, l);
    g_kfh[row * QKD + tid + 256] = h; g_kfl[row * QKD + tid + 256] = l;

    if (tid < 32) {
        const float x0 = src[KV_LORA + 2 * tid];
        const float x1 = src[KV_LORA + 2 * tid + 1];
        const float c = fcos[pos * 32 + tid];
        const float s = fsin[pos * 32 + tid];
        bsplit(x0 * c - x1 * s, h, l);
        g_kfh[row * QKD + KV_LORA + 2 * tid] = h;
        g_kfl[row * QKD + KV_LORA + 2 * tid] = l;
        bsplit(x0 * s + x1 * c, h, l);
        g_kfh[row * QKD + KV_LORA + 2 * tid + 1] = h;
        g_kfl[row * QKD + KV_LORA + 2 * tid + 1] = l;
    }
}

// ------------- q rope -------------------------------------------------------
__global__ void __launch_bounds__(512)
q_process_kernel(const float* __restrict__ fcos, const float* __restrict__ fsin)
{
    const long row = blockIdx.x;
    const int pos = (int)(row & (SEQ - 1));
    const int h = threadIdx.x / 32;
    const int i = threadIdx.x % 32;

    const long si = row * (N_HEADS * QK_HEAD) + h * QK_HEAD + NOPE + 2 * i;
    const float x0 = __bfloat162float(g_qh[si])     + __bfloat162float(g_ql[si]);
    const float x1 = __bfloat162float(g_qh[si + 1]) + __bfloat162float(g_ql[si + 1]);
    const float c = fcos[pos * 32 + i];
    const float s = fsin[pos * 32 + i];
    const long di = row * (N_HEADS * QKD) + h * QKD + KV_LORA + 2 * i;
    bf16 hh, ll;
    bsplit(x0 * c - x1 * s, hh, ll);
    g_qfh[di] = hh; g_qfl[di] = ll;
    bsplit(x0 * s + x1 * c, hh, ll);
    g_qfh[di + 1] = hh; g_qfl[di + 1] = ll;
}

// ------------- softmax (causal extent only) ---------------------------------
__global__ void __launch_bounds__(256)
softmax_mask_kernel(const float* __restrict__ mask)
{
    const long row = blockIdx.x;
    const int s = (int)(row & (SEQ - 1));
    const int T = ((s >> 7) + 1) << 7;
    const float* p = g_sc + row * SEQ;
    const float* mrow = mask + (long)s * SEQ;
    const int tid = threadIdx.x;
    const int t0 = tid * 8;
    const bool act = t0 < T;

    float v[8];
    float mx = -INFINITY;
    if (act) {
        const float4 a = reinterpret_cast<const float4*>(p + t0)[0];
        const float4 b = reinterpret_cast<const float4*>(p + t0)[1];
        const float4 ma = reinterpret_cast<const float4*>(mrow + t0)[0];
        const float4 mb = reinterpret_cast<const float4*>(mrow + t0)[1];
        v[0] = a.x + ma.x; v[1] = a.y + ma.y; v[2] = a.z + ma.z; v[3] = a.w + ma.w;
        v[4] = b.x + mb.x; v[5] = b.y + mb.y; v[6] = b.z + mb.z; v[7] = b.w + mb.w;
#pragma unroll
        for (int i = 0; i < 8; i++) mx = fmaxf(mx, v[i]);
    }
    __shared__ float red[256];
    red[tid] = mx; __syncthreads();
    for (int o = 128; o > 0; o >>= 1) {
        if (tid < o) red[tid] = fmaxf(red[tid], red[tid + o]);
        __syncthreads();
    }
    mx = red[0]; __syncthreads();

    float sum = 0.f;
    if (act) {
#pragma unroll
        for (int i = 0; i < 8; i++) { v[i] = expf(v[i] - mx); sum += v[i]; }
    }
    red[tid] = sum; __syncthreads();
    for (int o = 128; o > 0; o >>= 1) {
        if (tid < o) red[tid] += red[tid + o];
        __syncthreads();
    }
    const float inv = 1.f / red[0];

    if (act) {
#pragma unroll
        for (int i = 0; i < 4; i++) {
            bf16 h0, l0, h1, l1;
            bsplit(v[2 * i] * inv, h0, l0);
            bsplit(v[2 * i + 1] * inv, h1, l1);
            reinterpret_cast<__nv_bfloat162*>(g_Ph + row * SEQ + t0)[i]
                = __nv_bfloat162(h0, h1);
            reinterpret_cast<__nv_bfloat162*>(g_Pl + row * SEQ + t0)[i]
                = __nv_bfloat162(l0, l1);
        }
    }
}

// ---------------------------------------------------------------------------
extern "C" void kernel_launch(void* const* d_in, const int* in_sizes, int n_in,
                              void* d_out, int out_size)
{
    const float* x         = (const float*)d_in[0];
    const float* fcos      = (const float*)d_in[1];
    const float* fsin      = (const float*)d_in[2];
    const float* mask      = (const float*)d_in[3];
    const float* wq_a      = (const float*)d_in[4];
    const float* q_norm_w  = (const float*)d_in[5];
    const float* wq_b      = (const float*)d_in[6];
    const float* wkv_a     = (const float*)d_in[7];
    const float* kv_norm_w = (const float*)d_in[8];
    const float* wkv_b     = (const float*)d_in[9];
    const float* wo        = (const float*)d_in[10];
    float* out = (float*)d_out;

    bf16 *xh, *xl, *wqah, *wqal, *wqbh, *wqbl, *wkvah, *wkval, *wkvbh, *wkvbl;
    bf16 *woh, *wol, *qah, *qal, *qh, *ql, *kfh, *kfl, *vTh, *vTl, *wTh, *wTl;
    bf16 *qfh, *qfl, *Ph, *Pl, *ath, *atl, *o2h, *o2l;
    float *qaf, *kvf, *sc;
    cudaGetSymbolAddress((void**)&xh, g_xh);     cudaGetSymbolAddress((void**)&xl, g_xl);
    cudaGetSymbolAddress((void**)&wqah, g_wqah); cudaGetSymbolAddress((void**)&wqal, g_wqal);
    cudaGetSymbolAddress((void**)&wqbh, g_wqbh); cudaGetSymbolAddress((void**)&wqbl, g_wqbl);
    cudaGetSymbolAddress((void**)&wkvah, g_wkvah); cudaGetSymbolAddress((void**)&wkval, g_wkval);
    cudaGetSymbolAddress((void**)&wkvbh, g_wkvbh); cudaGetSymbolAddress((void**)&wkvbl, g_wkvbl);
    cudaGetSymbolAddress((void**)&woh, g_woh);   cudaGetSymbolAddress((void**)&wol, g_wol);
    cudaGetSymbolAddress((void**)&qaf, g_qa_f);
    cudaGetSymbolAddress((void**)&qah, g_qah);   cudaGetSymbolAddress((void**)&qal, g_qal);
    cudaGetSymbolAddress((void**)&qh, g_qh);     cudaGetSymbolAddress((void**)&ql, g_ql);
    cudaGetSymbolAddress((void**)&kvf, g_kv_f);
    cudaGetSymbolAddress((void**)&kfh, g_kfh);   cudaGetSymbolAddress((void**)&kfl, g_kfl);
    cudaGetSymbolAddress((void**)&vTh, g_vTh);   cudaGetSymbolAddress((void**)&vTl, g_vTl);
    cudaGetSymbolAddress((void**)&wTh, g_wTh);   cudaGetSymbolAddress((void**)&wTl, g_wTl);
    cudaGetSymbolAddress((void**)&qfh, g_qfh);   cudaGetSymbolAddress((void**)&qfl, g_qfl);
    cudaGetSymbolAddress((void**)&sc, g_sc);
    cudaGetSymbolAddress((void**)&Ph, g_Ph);     cudaGetSymbolAddress((void**)&Pl, g_Pl);
    cudaGetSymbolAddress((void**)&ath, g_ath);   cudaGetSymbolAddress((void**)&atl, g_atl);
    cudaGetSymbolAddress((void**)&o2h, g_o2h);   cudaGetSymbolAddress((void**)&o2l, g_o2l);

    cudaFuncSetAttribute(gemm_bf3<0>, cudaFuncAttributeMaxDynamicSharedMemorySize, SMEM_BYTES);
    cudaFuncSetAttribute(gemm_bf3<1>, cudaFuncAttributeMaxDynamicSharedMemorySize, SMEM_BYTES);

    dim3 blk(256);
    dim3 gblk(512);
    dim3 tb(32, 8);

    // 0. split inputs + weights
    auto splits = [&](const float* s, bf16* h, bf16* l, long n) {
        const long n4 = n / 4;
        int gs = (int)min((n4 + 255) / 256, (long)4096);
        split_kernel<<<gs, blk>>>(s, h, l, n4);
    };
    splits(x,     xh,    xl,    (long)ROWS * DIM);
    splits(wq_a,  wqah,  wqal,  (long)Q_LORA * DIM);
    splits(wq_b,  wqbh,  wqbl,  (long)N_HEADS * QK_HEAD * Q_LORA);
    splits(wkv_a, wkvah, wkval, (long)QKD * DIM);
    splits(wkv_b, wkvbh, wkvbl, (long)N_HEADS * 256 * KV_LORA);
    splits(wo,    woh,   wol,   (long)DIM * DIM);

    // 1. qa_f = x @ wq_a^T  (f32 out)
    gemm_bf3<0><<<dim3(ROWS/256, Q_LORA/128, 1), gblk, SMEM_BYTES>>>(
        xh, xl, wqah, wqal, qaf, nullptr, nullptr,
        ROWS, Q_LORA, DIM, DIM, DIM, Q_LORA, 0,0, 0,0, 0,0, 1, 1.f, 0);

    // 2. rmsnorm -> split qa
    rmsnorm_qa_kernel<<<ROWS, blk>>>(q_norm_w);

    // 3. q = qa @ wq_b^T  (split out)
    gemm_bf3<1><<<dim3(ROWS/256, (N_HEADS*QK_HEAD)/128, 1), gblk, SMEM_BYTES>>>(
        qah, qal, wqbh, wqbl, nullptr, qh, ql,
        ROWS, N_HEADS*QK_HEAD, Q_LORA, Q_LORA, Q_LORA, N_HEADS*QK_HEAD,
        0,0, 0,0, 0,0, 1, 1.f, 0);

    // 4. kv_f = x @ wkv_a^T  (f32 out)
    gemm_bf3<0><<<dim3(ROWS/256, (QKD+127)/128, 1), gblk, SMEM_BYTES>>>(
        xh, xl, wkvah, wkval, kvf, nullptr, nullptr,
        ROWS, QKD, DIM, DIM, DIM, QKD, 0,0, 0,0, 0,0, 1, 1.f, 0);

    // 5. kv -> split kf
    kv_process_kernel<<<ROWS, blk>>>(kv_norm_w, fcos, fsin);

    // 6. rope(q_pe) -> qf
    q_process_kernel<<<ROWS, 512>>>(fcos, fsin);

    // 6b/6c. transposes
    transpose_bf2<<<dim3(SEQ/32, KV_LORA/32, BATCH), tb>>>(
        kfh, kfl, vTh, vTl, QKD, SEQ, (long)SEQ*QKD, (long)KV_LORA*SEQ);
    transpose_bf2<<<dim3(NOPE/32, KV_LORA/32, N_HEADS), tb>>>(
        wkvbh, wkvbl, wTh, wTl, KV_LORA, NOPE, (long)256*KV_LORA, (long)KV_LORA*NOPE);

    // 7. qf[:,:,0:512] = q_nope @ wT[h]^T  (batched h)
    gemm_bf3<1><<<dim3(ROWS/256, KV_LORA/128, N_HEADS), gblk, SMEM_BYTES>>>(
        qh, ql, wTh, wTl, nullptr, qfh, qfl,
        ROWS, KV_LORA, NOPE, N_HEADS*QK_HEAD, NOPE, N_HEADS*QKD,
        0, QK_HEAD, 0, (long)KV_LORA*NOPE, 0, QKD, N_HEADS, 1.f, 0);

    // 8. scores = SCALE * qf @ kf^T  (causal tiles only)
    gemm_bf3<0><<<dim3(SEQ/256, SEQ/128, BATCH*N_HEADS), gblk, SMEM_BYTES>>>(
        qfh, qfl, kfh, kfl, sc, nullptr, nullptr,
        SEQ, SEQ, QKD, N_HEADS*QKD, QKD, SEQ,
        (long)SEQ*N_HEADS*QKD, QKD,
        (long)SEQ*QKD, 0,
        (long)N_HEADS*SEQ*SEQ, (long)SEQ*SEQ,
        N_HEADS, SCALE_F, 1);

    // 9. softmax -> split P (causal extent)
    softmax_mask_kernel<<<BATCH*N_HEADS*SEQ, blk>>>(mask);

    // 10. attno = P @ vT^T  (causal K bound)
    gemm_bf3<1><<<dim3(SEQ/256, KV_LORA/128, BATCH*N_HEADS), gblk, SMEM_BYTES>>>(
        Ph, Pl, vTh, vTl, nullptr, ath, atl,
        SEQ, KV_LORA, SEQ, SEQ, SEQ, N_HEADS*KV_LORA,
        (long)N_HEADS*SEQ*SEQ, (long)SEQ*SEQ,
        (long)KV_LORA*SEQ, 0,
        (long)SEQ*N_HEADS*KV_LORA, KV_LORA,
        N_HEADS, 1.f, 2);

    // 11. o2 = attno @ wkvb_v^T  (batched h)
    gemm_bf3<1><<<dim3(ROWS/256, V_HEAD/128, N_HEADS), gblk, SMEM_BYTES>>>(
        ath, atl, wkvbh + (size_t)NOPE*KV_LORA, wkvbl + (size_t)NOPE*KV_LORA,
        nullptr, o2h, o2l,
        ROWS, V_HEAD, KV_LORA, N_HEADS*KV_LORA, KV_LORA, DIM,
        0, KV_LORA, 0, (long)256*KV_LORA, 0, V_HEAD, N_HEADS, 1.f, 0);

    // 12. out = o2 @ wo^T  (f32 out)
    gemm_bf3<0><<<dim3(ROWS/256, DIM/128, 1), gblk, SMEM_BYTES>>>(
        o2h, o2l, woh, wol, out, nullptr, nullptr,
        ROWS, DIM, DIM, DIM, DIM, DIM, 0,0, 0,0, 0,0, 1, 1.f, 0);
}

// round 9
// speedup vs baseline: 1.1200x; 1.1106x over previous
#include <cuda_runtime.h>
#include <cuda_bf16.h>
#include <math.h>
#include <stdint.h>

// ---------------------------------------------------------------------------
// MLA forward. Split-bf16 3-term tensor-core GEMMs (Ah.Bh + Ah.Bl + Al.Bh).
// Round 9: smem-crossbar relief. CTA tile 256x128, 256 threads, 8 warps in
// 4(m) x 2(n), warp tile 64x64 -> ldmatrix:MMA ratio 1:6 (was 1:4) and
// cp.async writes amortized over 2x FLOPs. Round-6 2-stage double-buffer
// skeleton retained (rounds 7/8 proved deeper rings/more warps don't help).
// Causal block skipping retained. PTX-stable on compute_103 (no tcgen05).
// ---------------------------------------------------------------------------

#define DIM     2048
#define N_HEADS 16
#define Q_LORA  1536
#define KV_LORA 512
#define NOPE    128
#define ROPE    64
#define V_HEAD  128
#define QK_HEAD 192
#define BATCH   2
#define SEQ     2048
#define ROWS    (BATCH * SEQ)
#define QKD     (KV_LORA + ROPE)        // 576
#define SCALE_F 0.0721687836487032f
#define EPS_F   1e-6f

typedef __nv_bfloat16 bf16;

// ------------------------- scratch (device globals) -------------------------
__device__ __align__(256) bf16  g_xh   [(size_t)ROWS * DIM];
__device__ __align__(256) bf16  g_xl   [(size_t)ROWS * DIM];
__device__ __align__(256) bf16  g_wqah [(size_t)Q_LORA * DIM];
__device__ __align__(256) bf16  g_wqal [(size_t)Q_LORA * DIM];
__device__ __align__(256) bf16  g_wqbh [(size_t)N_HEADS * QK_HEAD * Q_LORA];
__device__ __align__(256) bf16  g_wqbl [(size_t)N_HEADS * QK_HEAD * Q_LORA];
__device__ __align__(256) bf16  g_wkvah[(size_t)QKD * DIM];
__device__ __align__(256) bf16  g_wkval[(size_t)QKD * DIM];
__device__ __align__(256) bf16  g_wkvbh[(size_t)N_HEADS * 256 * KV_LORA];
__device__ __align__(256) bf16  g_wkvbl[(size_t)N_HEADS * 256 * KV_LORA];
__device__ __align__(256) bf16  g_woh  [(size_t)DIM * DIM];
__device__ __align__(256) bf16  g_wol  [(size_t)DIM * DIM];

__device__ __align__(256) float g_qa_f [(size_t)ROWS * Q_LORA];
__device__ __align__(256) bf16  g_qah  [(size_t)ROWS * Q_LORA];
__device__ __align__(256) bf16  g_qal  [(size_t)ROWS * Q_LORA];
__device__ __align__(256) bf16  g_qh   [(size_t)ROWS * N_HEADS * QK_HEAD];
__device__ __align__(256) bf16  g_ql   [(size_t)ROWS * N_HEADS * QK_HEAD];
__device__ __align__(256) float g_kv_f [(size_t)ROWS * QKD];
__device__ __align__(256) bf16  g_kfh  [(size_t)ROWS * QKD];
__device__ __align__(256) bf16  g_kfl  [(size_t)ROWS * QKD];
__device__ __align__(256) bf16  g_vTh  [(size_t)BATCH * KV_LORA * SEQ];
__device__ __align__(256) bf16  g_vTl  [(size_t)BATCH * KV_LORA * SEQ];
__device__ __align__(256) bf16  g_wTh  [(size_t)N_HEADS * KV_LORA * NOPE];
__device__ __align__(256) bf16  g_wTl  [(size_t)N_HEADS * KV_LORA * NOPE];
__device__ __align__(256) bf16  g_qfh  [(size_t)ROWS * N_HEADS * QKD];
__device__ __align__(256) bf16  g_qfl  [(size_t)ROWS * N_HEADS * QKD];
__device__ __align__(256) float g_sc   [(size_t)BATCH * N_HEADS * SEQ * SEQ];
__device__ __align__(256) bf16  g_Ph   [(size_t)BATCH * N_HEADS * SEQ * SEQ];
__device__ __align__(256) bf16  g_Pl   [(size_t)BATCH * N_HEADS * SEQ * SEQ];
__device__ __align__(256) bf16  g_ath  [(size_t)ROWS * N_HEADS * KV_LORA];
__device__ __align__(256) bf16  g_atl  [(size_t)ROWS * N_HEADS * KV_LORA];
__device__ __align__(256) bf16  g_o2h  [(size_t)ROWS * DIM];
__device__ __align__(256) bf16  g_o2l  [(size_t)ROWS * DIM];

// ----------------------------- helpers --------------------------------------
__device__ __forceinline__ uint32_t smem_u32(const void* p) {
    uint32_t a;
    asm("{ .reg .u64 t; cvta.to.shared.u64 t, %1; cvt.u32.u64 %0, t; }"
        : "=r"(a) : "l"(p));
    return a;
}
__device__ __forceinline__ void cp16(uint32_t dst, const void* src) {
    asm volatile("cp.async.ca.shared.global [%0], [%1], 16;"
                 :: "r"(dst), "l"(src) : "memory");
}
#define CP_COMMIT() asm volatile("cp.async.commit_group;" ::: "memory")
#define CP_WAIT(n)  asm volatile("cp.async.wait_group %0;" :: "n"(n) : "memory")

__device__ __forceinline__ void ldm_x4(uint32_t* r, uint32_t addr) {
    asm volatile("ldmatrix.sync.aligned.m8n8.x4.shared.b16 {%0,%1,%2,%3}, [%4];"
                 : "=r"(r[0]), "=r"(r[1]), "=r"(r[2]), "=r"(r[3]) : "r"(addr));
}
__device__ __forceinline__ void mma_bf16(float* d, const uint32_t* a,
                                         const uint32_t* b) {
    asm volatile(
        "mma.sync.aligned.m16n8k16.row.col.f32.bf16.bf16.f32 "
        "{%0,%1,%2,%3}, {%4,%5,%6,%7}, {%8,%9}, {%0,%1,%2,%3};"
        : "+f"(d[0]), "+f"(d[1]), "+f"(d[2]), "+f"(d[3])
        : "r"(a[0]), "r"(a[1]), "r"(a[2]), "r"(a[3]), "r"(b[0]), "r"(b[1]));
}
__device__ __forceinline__ void bsplit(float x, bf16& h, bf16& l) {
    h = __float2bfloat16_rn(x);
    l = __float2bfloat16_rn(x - __bfloat162float(h));
}

// ----------------------- GEMM: C = alpha * A.B^T ----------------------------
// CTA tile 256x128, BK=32, 256 threads, warp tile 64x64 (4m x 2n warps).
// A,B pre-split bf16 hi/lo, K-major. M%256==0, K%32==0, N arbitrary.
// OUTM=0: C f32.  OUTM=1: C split to Ch/Cl bf16.
// mode bit0: skip tiles with n0 > m0+128 (causal scores)
// mode bit1: limit K to m0+256        (causal P.V)
#define ROWB 80
#define AT_B (256 * ROWB)                // 20480
#define BT_B (128 * ROWB)                // 10240
#define STG_B (2 * AT_B + 2 * BT_B)      // 61440: [Ah][Al][Bh][Bl]
#define SMEM_BYTES (2 * STG_B)           // 122880

__device__ __forceinline__ void load_tileA(uint32_t dst, const bf16* __restrict__ src,
                                           int ld, int k0, int tid) {
#pragma unroll
    for (int it = 0; it < 4; it++) {
        const int idx = tid + it * 256;
        const int row = idx >> 2, seg = idx & 3;
        cp16(dst + (uint32_t)(row * ROWB + seg * 16),
             src + (size_t)row * ld + k0 + seg * 8);
    }
}
__device__ __forceinline__ void load_tileB(uint32_t dst, const bf16* __restrict__ src,
                                           int ld, int k0, int limit, int tid) {
#pragma unroll
    for (int it = 0; it < 2; it++) {
        const int idx = tid + it * 256;
        const int row = idx >> 2, seg = idx & 3;
        const uint32_t d = dst + (uint32_t)(row * ROWB + seg * 16);
        if (row < limit) {
            cp16(d, src + (size_t)row * ld + k0 + seg * 8);
        } else {
            asm volatile("st.shared.v4.b32 [%0], {%1,%1,%1,%1};"
                         :: "r"(d), "r"(0) : "memory");
        }
    }
}
__device__ __forceinline__ void load_stage(uint32_t base,
                                           const bf16* Ath, const bf16* Atl,
                                           const bf16* Bth, const bf16* Btl,
                                           int lda, int ldb, int k0, int nlim, int tid) {
    load_tileA(base,                Ath, lda, k0, tid);
    load_tileA(base + AT_B,         Atl, lda, k0, tid);
    load_tileB(base + 2 * AT_B,        Bth, ldb, k0, nlim, tid);
    load_tileB(base + 2 * AT_B + BT_B, Btl, ldb, k0, nlim, tid);
}

template <int OUTM>
__global__ void __launch_bounds__(256)
gemm_bf3(const bf16* __restrict__ Ah, const bf16* __restrict__ Al,
         const bf16* __restrict__ Bh, const bf16* __restrict__ Bl,
         float* __restrict__ C, bf16* __restrict__ Ch, bf16* __restrict__ Cl,
         int M, int N, int K, int lda, int ldb, int ldc,
         long sAo, long sAi, long sBo, long sBi, long sCo, long sCi,
         int inner, float alpha, int mode)
{
    const int m0 = blockIdx.x * 256, n0 = blockIdx.y * 128;
    if ((mode & 1) && n0 > m0 + 128) return;    // causal tile skip

    extern __shared__ char smem[];
    const uint32_t sb = smem_u32(smem);
    const int tid = threadIdx.x, lane = tid & 31, wid = tid >> 5;
    const int wm = wid >> 1, wn = wid & 1;      // 4(m) x 2(n) warps, 64x64 tile
    const int g = lane >> 2, tig = lane & 3;

    const int z = blockIdx.z, zo = z / inner, zi = z - zo * inner;
    const long ofAB = (long)zo * sAo + (long)zi * sAi;
    const long ofB  = (long)zo * sBo + (long)zi * sBi;
    const long ofC  = (long)zo * sCo + (long)zi * sCi;
    Ah += ofAB; Al += ofAB;
    Bh += ofB;  Bl += ofB;

    const bf16* Ath = Ah + (size_t)m0 * lda;
    const bf16* Atl = Al + (size_t)m0 * lda;
    const bf16* Bth = Bh + (size_t)n0 * ldb;
    const bf16* Btl = Bl + (size_t)n0 * ldb;
    const int nlim = min(128, N - n0);

    float acc[4][8][4];
#pragma unroll
    for (int i = 0; i < 4; i++)
#pragma unroll
        for (int j = 0; j < 8; j++)
#pragma unroll
            for (int r = 0; r < 4; r++) acc[i][j][r] = 0.f;

    const int Keff = (mode & 2) ? min(K, m0 + 256) : K;
    const int nch = Keff >> 5;

    load_stage(sb, Ath, Atl, Bth, Btl, lda, ldb, 0, nlim, tid);
    CP_COMMIT();

    // warp tile 64(m) x 64(n)
    const uint32_t aoffL = (uint32_t)((wm * 64 + (lane & 15)) * ROWB + (lane >> 4) * 16);
    const uint32_t boffL = (uint32_t)((wn * 64 + ((lane >> 4) & 1) * 8 + (lane & 7)) * ROWB
                                      + ((lane >> 3) & 1) * 16);

    for (int c = 0; c < nch; c++) {
        if (c + 1 < nch) {
            load_stage(sb + ((c + 1) & 1) * STG_B, Ath, Atl, Bth, Btl,
                       lda, ldb, (c + 1) << 5, nlim, tid);
            CP_COMMIT();
            CP_WAIT(1);
        } else {
            CP_WAIT(0);
        }
        __syncthreads();

        const uint32_t base = sb + (c & 1) * STG_B;
        const uint32_t aA = base + aoffL;
        const uint32_t bA = base + 2 * AT_B + boffL;

#pragma unroll
        for (int ks = 0; ks < 2; ks++) {
            uint32_t bh[4][4], bl[4][4];
#pragma unroll
            for (int jj = 0; jj < 4; jj++) {
                ldm_x4(bh[jj], bA + ks * 32 + jj * 16 * ROWB);
                ldm_x4(bl[jj], bA + BT_B + ks * 32 + jj * 16 * ROWB);
            }
#pragma unroll
            for (int i = 0; i < 4; i++) {
                uint32_t ahf[4], alf[4];
                ldm_x4(ahf, aA + ks * 32 + i * 16 * ROWB);
                ldm_x4(alf, aA + AT_B + ks * 32 + i * 16 * ROWB);
#pragma unroll
                for (int j = 0; j < 8; j++) {
                    const uint32_t* bhp = &bh[j >> 1][(j & 1) * 2];
                    const uint32_t* blp = &bl[j >> 1][(j & 1) * 2];
                    mma_bf16(acc[i][j], alf, bhp);
                    mma_bf16(acc[i][j], ahf, blp);
                    mma_bf16(acc[i][j], ahf, bhp);
                }
            }
        }
        __syncthreads();
    }

    // epilogue
#pragma unroll
    for (int i = 0; i < 4; i++) {
        const int r0 = m0 + wm * 64 + i * 16 + g;
#pragma unroll
        for (int j = 0; j < 8; j++) {
            const int col = n0 + wn * 64 + j * 8 + tig * 2;
            if (col >= N) continue;
            const float c0 = alpha * acc[i][j][0], c1 = alpha * acc[i][j][1];
            const float c2 = alpha * acc[i][j][2], c3 = alpha * acc[i][j][3];
            if (OUTM == 0) {
                float* p0 = C + ofC + (size_t)r0 * ldc + col;
                float* p1 = C + ofC + (size_t)(r0 + 8) * ldc + col;
                if (col + 1 < N) {
                    *reinterpret_cast<float2*>(p0) = make_float2(c0, c1);
                    *reinterpret_cast<float2*>(p1) = make_float2(c2, c3);
                } else { p0[0] = c0; p1[0] = c2; }
            } else {
                bf16 h0, l0, h1, l1, h2, l2, h3, l3;
                bsplit(c0, h0, l0); bsplit(c1, h1, l1);
                bsplit(c2, h2, l2); bsplit(c3, h3, l3);
                *reinterpret_cast<__nv_bfloat162*>(Ch + ofC + (size_t)r0 * ldc + col)
                    = __nv_bfloat162(h0, h1);
                *reinterpret_cast<__nv_bfloat162*>(Cl + ofC + (size_t)r0 * ldc + col)
                    = __nv_bfloat162(l0, l1);
                *reinterpret_cast<__nv_bfloat162*>(Ch + ofC + (size_t)(r0 + 8) * ldc + col)
                    = __nv_bfloat162(h2, h3);
                *reinterpret_cast<__nv_bfloat162*>(Cl + ofC + (size_t)(r0 + 8) * ldc + col)
                    = __nv_bfloat162(l2, l3);
            }
        }
    }
}

// ---------------------- elementwise split f32 -> bf16 hi/lo ------------------
__global__ void __launch_bounds__(256)
split_kernel(const float* __restrict__ src, bf16* __restrict__ h,
             bf16* __restrict__ l, long n4)
{
    const long stride = (long)gridDim.x * blockDim.x;
    for (long i = blockIdx.x * (long)blockDim.x + threadIdx.x; i < n4; i += stride) {
        const float4 v = reinterpret_cast<const float4*>(src)[i];
        bf16 h0, l0, h1, l1, h2, l2, h3, l3;
        bsplit(v.x, h0, l0); bsplit(v.y, h1, l1);
        bsplit(v.z, h2, l2); bsplit(v.w, h3, l3);
        reinterpret_cast<__nv_bfloat162*>(h)[i * 2]     = __nv_bfloat162(h0, h1);
        reinterpret_cast<__nv_bfloat162*>(h)[i * 2 + 1] = __nv_bfloat162(h2, h3);
        reinterpret_cast<__nv_bfloat162*>(l)[i * 2]     = __nv_bfloat162(l0, l1);
        reinterpret_cast<__nv_bfloat162*>(l)[i * 2 + 1] = __nv_bfloat162(l2, l3);
    }
}

// ------------------- dual bf16 transpose (32x32 tiles) ----------------------
__global__ void __launch_bounds__(256)
transpose_bf2(const bf16* __restrict__ sh, const bf16* __restrict__ sl,
              bf16* __restrict__ dh, bf16* __restrict__ dl,
              int lds, int ldd, long sS, long sD)
{
    __shared__ float th[32][33], tl[32][33];
    const int z = blockIdx.z;
    sh += (long)z * sS; sl += (long)z * sS;
    dh += (long)z * sD; dl += (long)z * sD;
    const int r0 = blockIdx.x * 32, c0 = blockIdx.y * 32;
    const int tx = threadIdx.x, ty = threadIdx.y;
#pragma unroll
    for (int i = 0; i < 4; i++) {
        const long s = (long)(r0 + ty + 8 * i) * lds + c0 + tx;
        th[ty + 8 * i][tx] = __bfloat162float(sh[s]);
        tl[ty + 8 * i][tx] = __bfloat162float(sl[s]);
    }
    __syncthreads();
#pragma unroll
    for (int i = 0; i < 4; i++) {
        const long d = (long)(c0 + ty + 8 * i) * ldd + r0 + tx;
        dh[d] = __float2bfloat16_rn(th[tx][ty + 8 * i]);
        dl[d] = __float2bfloat16_rn(tl[tx][ty + 8 * i]);
    }
}

// --------------------------- rmsnorm: f32 -> split --------------------------
__global__ void __launch_bounds__(256)
rmsnorm_qa_kernel(const float* __restrict__ w)
{
    const long row = blockIdx.x;
    const float* p = g_qa_f + row * Q_LORA;
    const int tid = threadIdx.x;
    float v[6];
    float ss = 0.f;
#pragma unroll
    for (int i = 0; i < 6; i++) { v[i] = p[tid + i * 256]; ss += v[i] * v[i]; }
    __shared__ float red[256];
    red[tid] = ss; __syncthreads();
    for (int o = 128; o > 0; o >>= 1) {
        if (tid < o) red[tid] += red[tid + o];
        __syncthreads();
    }
    const float scale = rsqrtf(red[0] / (float)Q_LORA + EPS_F);
#pragma unroll
    for (int i = 0; i < 6; i++) {
        const int c = tid + i * 256;
        bf16 h, l;
        bsplit(v[i] * scale * w[c], h, l);
        g_qah[row * Q_LORA + c] = h;
        g_qal[row * Q_LORA + c] = l;
    }
}

// ------------- kv_process: f32 kv -> split kf (norm + rope) -----------------
__global__ void __launch_bounds__(256)
kv_process_kernel(const float* __restrict__ kv_norm_w,
                  const float* __restrict__ fcos,
                  const float* __restrict__ fsin)
{
    const long row = blockIdx.x;
    const int pos = (int)(row & (SEQ - 1));
    const float* src = g_kv_f + row * QKD;
    const int tid = threadIdx.x;

    const float v0 = src[tid], v1 = src[tid + 256];
    __shared__ float red[256];
    red[tid] = v0 * v0 + v1 * v1; __syncthreads();
    for (int o = 128; o > 0; o >>= 1) {
        if (tid < o) red[tid] += red[tid + o];
        __syncthreads();
    }
    const float scale = rsqrtf(red[0] / (float)KV_LORA + EPS_F);
    bf16 h, l;
    bsplit(v0 * scale * kv_norm_w[tid], h, l);
    g_kfh[row * QKD + tid] = h; g_kfl[row * QKD + tid] = l;
    bsplit(v1 * scale * kv_norm_w[tid + 256], h, l);
    g_kfh[row * QKD + tid + 256] = h; g_kfl[row * QKD + tid + 256] = l;

    if (tid < 32) {
        const float x0 = src[KV_LORA + 2 * tid];
        const float x1 = src[KV_LORA + 2 * tid + 1];
        const float c = fcos[pos * 32 + tid];
        const float s = fsin[pos * 32 + tid];
        bsplit(x0 * c - x1 * s, h, l);
        g_kfh[row * QKD + KV_LORA + 2 * tid] = h;
        g_kfl[row * QKD + KV_LORA + 2 * tid] = l;
        bsplit(x0 * s + x1 * c, h, l);
        g_kfh[row * QKD + KV_LORA + 2 * tid + 1] = h;
        g_kfl[row * QKD + KV_LORA + 2 * tid + 1] = l;
    }
}

// ------------- q rope -------------------------------------------------------
__global__ void __launch_bounds__(512)
q_process_kernel(const float* __restrict__ fcos, const float* __restrict__ fsin)
{
    const long row = blockIdx.x;
    const int pos = (int)(row & (SEQ - 1));
    const int h = threadIdx.x / 32;
    const int i = threadIdx.x % 32;

    const long si = row * (N_HEADS * QK_HEAD) + h * QK_HEAD + NOPE + 2 * i;
    const float x0 = __bfloat162float(g_qh[si])     + __bfloat162float(g_ql[si]);
    const float x1 = __bfloat162float(g_qh[si + 1]) + __bfloat162float(g_ql[si + 1]);
    const float c = fcos[pos * 32 + i];
    const float s = fsin[pos * 32 + i];
    const long di = row * (N_HEADS * QKD) + h * QKD + KV_LORA + 2 * i;
    bf16 hh, ll;
    bsplit(x0 * c - x1 * s, hh, ll);
    g_qfh[di] = hh; g_qfl[di] = ll;
    bsplit(x0 * s + x1 * c, hh, ll);
    g_qfh[di + 1] = hh; g_qfl[di + 1] = ll;
}

// ------------- softmax (causal extent only) ---------------------------------
__global__ void __launch_bounds__(256)
softmax_mask_kernel(const float* __restrict__ mask)
{
    const long row = blockIdx.x;
    const int s = (int)(row & (SEQ - 1));
    const int T = ((s >> 7) + 1) << 7;
    const float* p = g_sc + row * SEQ;
    const float* mrow = mask + (long)s * SEQ;
    const int tid = threadIdx.x;
    const int t0 = tid * 8;
    const bool act = t0 < T;

    float v[8];
    float mx = -INFINITY;
    if (act) {
        const float4 a = reinterpret_cast<const float4*>(p + t0)[0];
        const float4 b = reinterpret_cast<const float4*>(p + t0)[1];
        const float4 ma = reinterpret_cast<const float4*>(mrow + t0)[0];
        const float4 mb = reinterpret_cast<const float4*>(mrow + t0)[1];
        v[0] = a.x + ma.x; v[1] = a.y + ma.y; v[2] = a.z + ma.z; v[3] = a.w + ma.w;
        v[4] = b.x + mb.x; v[5] = b.y + mb.y; v[6] = b.z + mb.z; v[7] = b.w + mb.w;
#pragma unroll
        for (int i = 0; i < 8; i++) mx = fmaxf(mx, v[i]);
    }
    __shared__ float red[256];
    red[tid] = mx; __syncthreads();
    for (int o = 128; o > 0; o >>= 1) {
        if (tid < o) red[tid] = fmaxf(red[tid], red[tid + o]);
        __syncthreads();
    }
    mx = red[0]; __syncthreads();

    float sum = 0.f;
    if (act) {
#pragma unroll
        for (int i = 0; i < 8; i++) { v[i] = expf(v[i] - mx); sum += v[i]; }
    }
    red[tid] = sum; __syncthreads();
    for (int o = 128; o > 0; o >>= 1) {
        if (tid < o) red[tid] += red[tid + o];
        __syncthreads();
    }
    const float inv = 1.f / red[0];

    if (act) {
#pragma unroll
        for (int i = 0; i < 4; i++) {
            bf16 h0, l0, h1, l1;
            bsplit(v[2 * i] * inv, h0, l0);
            bsplit(v[2 * i + 1] * inv, h1, l1);
            reinterpret_cast<__nv_bfloat162*>(g_Ph + row * SEQ + t0)[i]
                = __nv_bfloat162(h0, h1);
            reinterpret_cast<__nv_bfloat162*>(g_Pl + row * SEQ + t0)[i]
                = __nv_bfloat162(l0, l1);
        }
    }
}

// ---------------------------------------------------------------------------
extern "C" void kernel_launch(void* const* d_in, const int* in_sizes, int n_in,
                              void* d_out, int out_size)
{
    const float* x         = (const float*)d_in[0];
    const float* fcos      = (const float*)d_in[1];
    const float* fsin      = (const float*)d_in[2];
    const float* mask      = (const float*)d_in[3];
    const float* wq_a      = (const float*)d_in[4];
    const float* q_norm_w  = (const float*)d_in[5];
    const float* wq_b      = (const float*)d_in[6];
    const float* wkv_a     = (const float*)d_in[7];
    const float* kv_norm_w = (const float*)d_in[8];
    const float* wkv_b     = (const float*)d_in[9];
    const float* wo        = (const float*)d_in[10];
    float* out = (float*)d_out;

    bf16 *xh, *xl, *wqah, *wqal, *wqbh, *wqbl, *wkvah, *wkval, *wkvbh, *wkvbl;
    bf16 *woh, *wol, *qah, *qal, *qh, *ql, *kfh, *kfl, *vTh, *vTl, *wTh, *wTl;
    bf16 *qfh, *qfl, *Ph, *Pl, *ath, *atl, *o2h, *o2l;
    float *qaf, *kvf, *sc;
    cudaGetSymbolAddress((void**)&xh, g_xh);     cudaGetSymbolAddress((void**)&xl, g_xl);
    cudaGetSymbolAddress((void**)&wqah, g_wqah); cudaGetSymbolAddress((void**)&wqal, g_wqal);
    cudaGetSymbolAddress((void**)&wqbh, g_wqbh); cudaGetSymbolAddress((void**)&wqbl, g_wqbl);
    cudaGetSymbolAddress((void**)&wkvah, g_wkvah); cudaGetSymbolAddress((void**)&wkval, g_wkval);
    cudaGetSymbolAddress((void**)&wkvbh, g_wkvbh); cudaGetSymbolAddress((void**)&wkvbl, g_wkvbl);
    cudaGetSymbolAddress((void**)&woh, g_woh);   cudaGetSymbolAddress((void**)&wol, g_wol);
    cudaGetSymbolAddress((void**)&qaf, g_qa_f);
    cudaGetSymbolAddress((void**)&qah, g_qah);   cudaGetSymbolAddress((void**)&qal, g_qal);
    cudaGetSymbolAddress((void**)&qh, g_qh);     cudaGetSymbolAddress((void**)&ql, g_ql);
    cudaGetSymbolAddress((void**)&kvf, g_kv_f);
    cudaGetSymbolAddress((void**)&kfh, g_kfh);   cudaGetSymbolAddress((void**)&kfl, g_kfl);
    cudaGetSymbolAddress((void**)&vTh, g_vTh);   cudaGetSymbolAddress((void**)&vTl, g_vTl);
    cudaGetSymbolAddress((void**)&wTh, g_wTh);   cudaGetSymbolAddress((void**)&wTl, g_wTl);
    cudaGetSymbolAddress((void**)&qfh, g_qfh);   cudaGetSymbolAddress((void**)&qfl, g_qfl);
    cudaGetSymbolAddress((void**)&sc, g_sc);
    cudaGetSymbolAddress((void**)&Ph, g_Ph);     cudaGetSymbolAddress((void**)&Pl, g_Pl);
    cudaGetSymbolAddress((void**)&ath, g_ath);   cudaGetSymbolAddress((void**)&atl, g_atl);
    cudaGetSymbolAddress((void**)&o2h, g_o2h);   cudaGetSymbolAddress((void**)&o2l, g_o2l);

    cudaFuncSetAttribute(gemm_bf3<0>, cudaFuncAttributeMaxDynamicSharedMemorySize, SMEM_BYTES);
    cudaFuncSetAttribute(gemm_bf3<1>, cudaFuncAttributeMaxDynamicSharedMemorySize, SMEM_BYTES);

    dim3 blk(256);
    dim3 tb(32, 8);

    // 0. split inputs + weights
    auto splits = [&](const float* s, bf16* h, bf16* l, long n) {
        const long n4 = n / 4;
        int gs = (int)min((n4 + 255) / 256, (long)4096);
        split_kernel<<<gs, blk>>>(s, h, l, n4);
    };
    splits(x,     xh,    xl,    (long)ROWS * DIM);
    splits(wq_a,  wqah,  wqal,  (long)Q_LORA * DIM);
    splits(wq_b,  wqbh,  wqbl,  (long)N_HEADS * QK_HEAD * Q_LORA);
    splits(wkv_a, wkvah, wkval, (long)QKD * DIM);
    splits(wkv_b, wkvbh, wkvbl, (long)N_HEADS * 256 * KV_LORA);
    splits(wo,    woh,   wol,   (long)DIM * DIM);

    // 1. qa_f = x @ wq_a^T  (f32 out)
    gemm_bf3<0><<<dim3(ROWS/256, Q_LORA/128, 1), blk, SMEM_BYTES>>>(
        xh, xl, wqah, wqal, qaf, nullptr, nullptr,
        ROWS, Q_LORA, DIM, DIM, DIM, Q_LORA, 0,0, 0,0, 0,0, 1, 1.f, 0);

    // 2. rmsnorm -> split qa
    rmsnorm_qa_kernel<<<ROWS, blk>>>(q_norm_w);

    // 3. q = qa @ wq_b^T  (split out)
    gemm_bf3<1><<<dim3(ROWS/256, (N_HEADS*QK_HEAD)/128, 1), blk, SMEM_BYTES>>>(
        qah, qal, wqbh, wqbl, nullptr, qh, ql,
        ROWS, N_HEADS*QK_HEAD, Q_LORA, Q_LORA, Q_LORA, N_HEADS*QK_HEAD,
        0,0, 0,0, 0,0, 1, 1.f, 0);

    // 4. kv_f = x @ wkv_a^T  (f32 out)
    gemm_bf3<0><<<dim3(ROWS/256, (QKD+127)/128, 1), blk, SMEM_BYTES>>>(
        xh, xl, wkvah, wkval, kvf, nullptr, nullptr,
        ROWS, QKD, DIM, DIM, DIM, QKD, 0,0, 0,0, 0,0, 1, 1.f, 0);

    // 5. kv -> split kf
    kv_process_kernel<<<ROWS, blk>>>(kv_norm_w, fcos, fsin);

    // 6. rope(q_pe) -> qf
    q_process_kernel<<<ROWS, 512>>>(fcos, fsin);

    // 6b/6c. transposes
    transpose_bf2<<<dim3(SEQ/32, KV_LORA/32, BATCH), tb>>>(
        kfh, kfl, vTh, vTl, QKD, SEQ, (long)SEQ*QKD, (long)KV_LORA*SEQ);
    transpose_bf2<<<dim3(NOPE/32, KV_LORA/32, N_HEADS), tb>>>(
        wkvbh, wkvbl, wTh, wTl, KV_LORA, NOPE, (long)256*KV_LORA, (long)KV_LORA*NOPE);

    // 7. qf[:,:,0:512] = q_nope @ wT[h]^T  (batched h)
    gemm_bf3<1><<<dim3(ROWS/256, KV_LORA/128, N_HEADS), blk, SMEM_BYTES>>>(
        qh, ql, wTh, wTl, nullptr, qfh, qfl,
        ROWS, KV_LORA, NOPE, N_HEADS*QK_HEAD, NOPE, N_HEADS*QKD,
        0, QK_HEAD, 0, (long)KV_LORA*NOPE, 0, QKD, N_HEADS, 1.f, 0);

    // 8. scores = SCALE * qf @ kf^T  (causal tiles only)
    gemm_bf3<0><<<dim3(SEQ/256, SEQ/128, BATCH*N_HEADS), blk, SMEM_BYTES>>>(
        qfh, qfl, kfh, kfl, sc, nullptr, nullptr,
        SEQ, SEQ, QKD, N_HEADS*QKD, QKD, SEQ,
        (long)SEQ*N_HEADS*QKD, QKD,
        (long)SEQ*QKD, 0,
        (long)N_HEADS*SEQ*SEQ, (long)SEQ*SEQ,
        N_HEADS, SCALE_F, 1);

    // 9. softmax -> split P (causal extent)
    softmax_mask_kernel<<<BATCH*N_HEADS*SEQ, blk>>>(mask);

    // 10. attno = P @ vT^T  (causal K bound)
    gemm_bf3<1><<<dim3(SEQ/256, KV_LORA/128, BATCH*N_HEADS), blk, SMEM_BYTES>>>(
        Ph, Pl, vTh, vTl, nullptr, ath, atl,
        SEQ, KV_LORA, SEQ, SEQ, SEQ, N_HEADS*KV_LORA,
        (long)N_HEADS*SEQ*SEQ, (long)SEQ*SEQ,
        (long)KV_LORA*SEQ, 0,
        (long)SEQ*N_HEADS*KV_LORA, KV_LORA,
        N_HEADS, 1.f, 2);

    // 11. o2 = attno @ wkvb_v^T  (batched h)
    gemm_bf3<1><<<dim3(ROWS/256, V_HEAD/128, N_HEADS), blk, SMEM_BYTES>>>(
        ath, atl, wkvbh + (size_t)NOPE*KV_LORA, wkvbl + (size_t)NOPE*KV_LORA,
        nullptr, o2h, o2l,
        ROWS, V_HEAD, KV_LORA, N_HEADS*KV_LORA, KV_LORA, DIM,
        0, KV_LORA, 0, (long)256*KV_LORA, 0, V_HEAD, N_HEADS, 1.f, 0);

    // 12. out = o2 @ wo^T  (f32 out)
    gemm_bf3<0><<<dim3(ROWS/256, DIM/128, 1), blk, SMEM_BYTES>>>(
        o2h, o2l, woh, wol, out, nullptr, nullptr,
        ROWS, DIM, DIM, DIM, DIM, DIM, 0,0, 0,0, 0,0, 1, 1.f, 0);
}

// round 10
// speedup vs baseline: 1.6070x; 1.4348x over previous
#include <cuda_runtime.h>
#include <cuda_bf16.h>
#include <math.h>
#include <stdint.h>

// ---------------------------------------------------------------------------
// MLA forward. Split-bf16 3-term tensor-core GEMMs (Ah.Bh + Ah.Bl + Al.Bh).
// Round 10: DE-ABSORBED attention (prefill-optimal association):
//   k_eff[b,h] = kv_cache @ wkvb_nope^T   (per-head 128-dim keys)
//   scores     = [q_nope|q_pe] . [k_eff|k_pe]^T   (K=192, was 576)
//   v_eff[b,h] = kv_cache @ wkvb_v^T
//   o2         = P @ v_eff^T              (K=t, N=128; was K=t,N=512 + extra GEMM)
// 40% fewer issued MMA-FLOPs at identical math. GEMM kernel = round-9
// (256x128 CTA, 64x64 warp tile, double-buffered cp.async, causal skipping).
// PTX-stable on compute_103 (no tcgen05).
// ---------------------------------------------------------------------------

#define DIM     2048
#define N_HEADS 16
#define Q_LORA  1536
#define KV_LORA 512
#define NOPE    128
#define ROPE    64
#define V_HEAD  128
#define QK_HEAD 192
#define BATCH   2
#define SEQ     2048
#define ROWS    (BATCH * SEQ)
#define QKD     (KV_LORA + ROPE)        // 576
#define NBH     (BATCH * N_HEADS)       // 32
#define SCALE_F 0.0721687836487032f
#define EPS_F   1e-6f

typedef __nv_bfloat16 bf16;

// ------------------------- scratch (device globals) -------------------------
__device__ __align__(256) bf16  g_xh   [(size_t)ROWS * DIM];
__device__ __align__(256) bf16  g_xl   [(size_t)ROWS * DIM];
__device__ __align__(256) bf16  g_wqah [(size_t)Q_LORA * DIM];
__device__ __align__(256) bf16  g_wqal [(size_t)Q_LORA * DIM];
__device__ __align__(256) bf16  g_wqbh [(size_t)N_HEADS * QK_HEAD * Q_LORA];
__device__ __align__(256) bf16  g_wqbl [(size_t)N_HEADS * QK_HEAD * Q_LORA];
__device__ __align__(256) bf16  g_wkvah[(size_t)QKD * DIM];
__device__ __align__(256) bf16  g_wkval[(size_t)QKD * DIM];
__device__ __align__(256) bf16  g_wkvbh[(size_t)N_HEADS * 256 * KV_LORA];
__device__ __align__(256) bf16  g_wkvbl[(size_t)N_HEADS * 256 * KV_LORA];
__device__ __align__(256) bf16  g_woh  [(size_t)DIM * DIM];
__device__ __align__(256) bf16  g_wol  [(size_t)DIM * DIM];

__device__ __align__(256) float g_qa_f [(size_t)ROWS * Q_LORA];
__device__ __align__(256) bf16  g_qah  [(size_t)ROWS * Q_LORA];
__device__ __align__(256) bf16  g_qal  [(size_t)ROWS * Q_LORA];
__device__ __align__(256) bf16  g_qh   [(size_t)ROWS * N_HEADS * QK_HEAD];
__device__ __align__(256) bf16  g_ql   [(size_t)ROWS * N_HEADS * QK_HEAD];
__device__ __align__(256) float g_kv_f [(size_t)ROWS * QKD];
__device__ __align__(256) bf16  g_kfh  [(size_t)ROWS * QKD];
__device__ __align__(256) bf16  g_kfl  [(size_t)ROWS * QKD];

__device__ __align__(256) bf16  g_keh  [(size_t)NBH * SEQ * QK_HEAD];  // [b,h][t][192]
__device__ __align__(256) bf16  g_kel  [(size_t)NBH * SEQ * QK_HEAD];
__device__ __align__(256) bf16  g_veh  [(size_t)NBH * SEQ * V_HEAD];   // [b,h][t][128]
__device__ __align__(256) bf16  g_vel  [(size_t)NBH * SEQ * V_HEAD];
__device__ __align__(256) bf16  g_vTh  [(size_t)NBH * V_HEAD * SEQ];   // [b,h][128][t]
__device__ __align__(256) bf16  g_vTl  [(size_t)NBH * V_HEAD * SEQ];

__device__ __align__(256) float g_sc   [(size_t)NBH * SEQ * SEQ];
__device__ __align__(256) bf16  g_Ph   [(size_t)NBH * SEQ * SEQ];
__device__ __align__(256) bf16  g_Pl   [(size_t)NBH * SEQ * SEQ];
__device__ __align__(256) bf16  g_o2h  [(size_t)ROWS * DIM];
__device__ __align__(256) bf16  g_o2l  [(size_t)ROWS * DIM];

// ----------------------------- helpers --------------------------------------
__device__ __forceinline__ uint32_t smem_u32(const void* p) {
    uint32_t a;
    asm("{ .reg .u64 t; cvta.to.shared.u64 t, %1; cvt.u32.u64 %0, t; }"
        : "=r"(a) : "l"(p));
    return a;
}
__device__ __forceinline__ void cp16(uint32_t dst, const void* src) {
    asm volatile("cp.async.ca.shared.global [%0], [%1], 16;"
                 :: "r"(dst), "l"(src) : "memory");
}
#define CP_COMMIT() asm volatile("cp.async.commit_group;" ::: "memory")
#define CP_WAIT(n)  asm volatile("cp.async.wait_group %0;" :: "n"(n) : "memory")

__device__ __forceinline__ void ldm_x4(uint32_t* r, uint32_t addr) {
    asm volatile("ldmatrix.sync.aligned.m8n8.x4.shared.b16 {%0,%1,%2,%3}, [%4];"
                 : "=r"(r[0]), "=r"(r[1]), "=r"(r[2]), "=r"(r[3]) : "r"(addr));
}
__device__ __forceinline__ void mma_bf16(float* d, const uint32_t* a,
                                         const uint32_t* b) {
    asm volatile(
        "mma.sync.aligned.m16n8k16.row.col.f32.bf16.bf16.f32 "
        "{%0,%1,%2,%3}, {%4,%5,%6,%7}, {%8,%9}, {%0,%1,%2,%3};"
        : "+f"(d[0]), "+f"(d[1]), "+f"(d[2]), "+f"(d[3])
        : "r"(a[0]), "r"(a[1]), "r"(a[2]), "r"(a[3]), "r"(b[0]), "r"(b[1]));
}
__device__ __forceinline__ void bsplit(float x, bf16& h, bf16& l) {
    h = __float2bfloat16_rn(x);
    l = __float2bfloat16_rn(x - __bfloat162float(h));
}

// ----------------------- GEMM: C = alpha * A.B^T ----------------------------
// CTA tile 256x128, BK=32, 256 threads, warp tile 64x64 (4m x 2n warps).
// A,B pre-split bf16 hi/lo, K-major. M%256==0, K%32==0, N arbitrary.
// OUTM=0: C f32.  OUTM=1: C split to Ch/Cl bf16.
// mode bit0: skip tiles with n0 > m0+128 (causal scores)
// mode bit1: limit K to m0+256        (causal P.V)
#define ROWB 80
#define AT_B (256 * ROWB)
#define BT_B (128 * ROWB)
#define STG_B (2 * AT_B + 2 * BT_B)      // 61440
#define SMEM_BYTES (2 * STG_B)           // 122880

__device__ __forceinline__ void load_tileA(uint32_t dst, const bf16* __restrict__ src,
                                           int ld, int k0, int tid) {
#pragma unroll
    for (int it = 0; it < 4; it++) {
        const int idx = tid + it * 256;
        const int row = idx >> 2, seg = idx & 3;
        cp16(dst + (uint32_t)(row * ROWB + seg * 16),
             src + (size_t)row * ld + k0 + seg * 8);
    }
}
__device__ __forceinline__ void load_tileB(uint32_t dst, const bf16* __restrict__ src,
                                           int ld, int k0, int limit, int tid) {
#pragma unroll
    for (int it = 0; it < 2; it++) {
        const int idx = tid + it * 256;
        const int row = idx >> 2, seg = idx & 3;
        const uint32_t d = dst + (uint32_t)(row * ROWB + seg * 16);
        if (row < limit) {
            cp16(d, src + (size_t)row * ld + k0 + seg * 8);
        } else {
            asm volatile("st.shared.v4.b32 [%0], {%1,%1,%1,%1};"
                         :: "r"(d), "r"(0) : "memory");
        }
    }
}
__device__ __forceinline__ void load_stage(uint32_t base,
                                           const bf16* Ath, const bf16* Atl,
                                           const bf16* Bth, const bf16* Btl,
                                           int lda, int ldb, int k0, int nlim, int tid) {
    load_tileA(base,                Ath, lda, k0, tid);
    load_tileA(base + AT_B,         Atl, lda, k0, tid);
    load_tileB(base + 2 * AT_B,        Bth, ldb, k0, nlim, tid);
    load_tileB(base + 2 * AT_B + BT_B, Btl, ldb, k0, nlim, tid);
}

template <int OUTM>
__global__ void __launch_bounds__(256)
gemm_bf3(const bf16* __restrict__ Ah, const bf16* __restrict__ Al,
         const bf16* __restrict__ Bh, const bf16* __restrict__ Bl,
         float* __restrict__ C, bf16* __restrict__ Ch, bf16* __restrict__ Cl,
         int M, int N, int K, int lda, int ldb, int ldc,
         long sAo, long sAi, long sBo, long sBi, long sCo, long sCi,
         int inner, float alpha, int mode)
{
    const int m0 = blockIdx.x * 256, n0 = blockIdx.y * 128;
    if ((mode & 1) && n0 > m0 + 128) return;

    extern __shared__ char smem[];
    const uint32_t sb = smem_u32(smem);
    const int tid = threadIdx.x, lane = tid & 31, wid = tid >> 5;
    const int wm = wid >> 1, wn = wid & 1;
    const int g = lane >> 2, tig = lane & 3;

    const int z = blockIdx.z, zo = z / inner, zi = z - zo * inner;
    const long ofA = (long)zo * sAo + (long)zi * sAi;
    const long ofB = (long)zo * sBo + (long)zi * sBi;
    const long ofC = (long)zo * sCo + (long)zi * sCi;
    Ah += ofA; Al += ofA;
    Bh += ofB; Bl += ofB;

    const bf16* Ath = Ah + (size_t)m0 * lda;
    const bf16* Atl = Al + (size_t)m0 * lda;
    const bf16* Bth = Bh + (size_t)n0 * ldb;
    const bf16* Btl = Bl + (size_t)n0 * ldb;
    const int nlim = min(128, N - n0);

    float acc[4][8][4];
#pragma unroll
    for (int i = 0; i < 4; i++)
#pragma unroll
        for (int j = 0; j < 8; j++)
#pragma unroll
            for (int r = 0; r < 4; r++) acc[i][j][r] = 0.f;

    const int Keff = (mode & 2) ? min(K, m0 + 256) : K;
    const int nch = Keff >> 5;

    load_stage(sb, Ath, Atl, Bth, Btl, lda, ldb, 0, nlim, tid);
    CP_COMMIT();

    const uint32_t aoffL = (uint32_t)((wm * 64 + (lane & 15)) * ROWB + (lane >> 4) * 16);
    const uint32_t boffL = (uint32_t)((wn * 64 + ((lane >> 4) & 1) * 8 + (lane & 7)) * ROWB
                                      + ((lane >> 3) & 1) * 16);

    for (int c = 0; c < nch; c++) {
        if (c + 1 < nch) {
            load_stage(sb + ((c + 1) & 1) * STG_B, Ath, Atl, Bth, Btl,
                       lda, ldb, (c + 1) << 5, nlim, tid);
            CP_COMMIT();
            CP_WAIT(1);
        } else {
            CP_WAIT(0);
        }
        __syncthreads();

        const uint32_t base = sb + (c & 1) * STG_B;
        const uint32_t aA = base + aoffL;
        const uint32_t bA = base + 2 * AT_B + boffL;

#pragma unroll
        for (int ks = 0; ks < 2; ks++) {
            uint32_t bh[4][4], bl[4][4];
#pragma unroll
            for (int jj = 0; jj < 4; jj++) {
                ldm_x4(bh[jj], bA + ks * 32 + jj * 16 * ROWB);
                ldm_x4(bl[jj], bA + BT_B + ks * 32 + jj * 16 * ROWB);
            }
#pragma unroll
            for (int i = 0; i < 4; i++) {
                uint32_t ahf[4], alf[4];
                ldm_x4(ahf, aA + ks * 32 + i * 16 * ROWB);
                ldm_x4(alf, aA + AT_B + ks * 32 + i * 16 * ROWB);
#pragma unroll
                for (int j = 0; j < 8; j++) {
                    const uint32_t* bhp = &bh[j >> 1][(j & 1) * 2];
                    const uint32_t* blp = &bl[j >> 1][(j & 1) * 2];
                    mma_bf16(acc[i][j], alf, bhp);
                    mma_bf16(acc[i][j], ahf, blp);
                    mma_bf16(acc[i][j], ahf, bhp);
                }
            }
        }
        __syncthreads();
    }

    // epilogue
#pragma unroll
    for (int i = 0; i < 4; i++) {
        const int r0 = m0 + wm * 64 + i * 16 + g;
#pragma unroll
        for (int j = 0; j < 8; j++) {
            const int col = n0 + wn * 64 + j * 8 + tig * 2;
            if (col >= N) continue;
            const float c0 = alpha * acc[i][j][0], c1 = alpha * acc[i][j][1];
            const float c2 = alpha * acc[i][j][2], c3 = alpha * acc[i][j][3];
            if (OUTM == 0) {
                float* p0 = C + ofC + (size_t)r0 * ldc + col;
                float* p1 = C + ofC + (size_t)(r0 + 8) * ldc + col;
                if (col + 1 < N) {
                    *reinterpret_cast<float2*>(p0) = make_float2(c0, c1);
                    *reinterpret_cast<float2*>(p1) = make_float2(c2, c3);
                } else { p0[0] = c0; p1[0] = c2; }
            } else {
                bf16 h0, l0, h1, l1, h2, l2, h3, l3;
                bsplit(c0, h0, l0); bsplit(c1, h1, l1);
                bsplit(c2, h2, l2); bsplit(c3, h3, l3);
                *reinterpret_cast<__nv_bfloat162*>(Ch + ofC + (size_t)r0 * ldc + col)
                    = __nv_bfloat162(h0, h1);
                *reinterpret_cast<__nv_bfloat162*>(Cl + ofC + (size_t)r0 * ldc + col)
                    = __nv_bfloat162(l0, l1);
                *reinterpret_cast<__nv_bfloat162*>(Ch + ofC + (size_t)(r0 + 8) * ldc + col)
                    = __nv_bfloat162(h2, h3);
                *reinterpret_cast<__nv_bfloat162*>(Cl + ofC + (size_t)(r0 + 8) * ldc + col)
                    = __nv_bfloat162(l2, l3);
            }
        }
    }
}

// ---------------------- elementwise split f32 -> bf16 hi/lo ------------------
__global__ void __launch_bounds__(256)
split_kernel(const float* __restrict__ src, bf16* __restrict__ h,
             bf16* __restrict__ l, long n4)
{
    const long stride = (long)gridDim.x * blockDim.x;
    for (long i = blockIdx.x * (long)blockDim.x + threadIdx.x; i < n4; i += stride) {
        const float4 v = reinterpret_cast<const float4*>(src)[i];
        bf16 h0, l0, h1, l1, h2, l2, h3, l3;
        bsplit(v.x, h0, l0); bsplit(v.y, h1, l1);
        bsplit(v.z, h2, l2); bsplit(v.w, h3, l3);
        reinterpret_cast<__nv_bfloat162*>(h)[i * 2]     = __nv_bfloat162(h0, h1);
        reinterpret_cast<__nv_bfloat162*>(h)[i * 2 + 1] = __nv_bfloat162(h2, h3);
        reinterpret_cast<__nv_bfloat162*>(l)[i * 2]     = __nv_bfloat162(l0, l1);
        reinterpret_cast<__nv_bfloat162*>(l)[i * 2 + 1] = __nv_bfloat162(l2, l3);
    }
}

// ------------------- dual bf16 transpose (32x32 tiles) ----------------------
__global__ void __launch_bounds__(256)
transpose_bf2(const bf16* __restrict__ sh, const bf16* __restrict__ sl,
              bf16* __restrict__ dh, bf16* __restrict__ dl,
              int lds, int ldd, long sS, long sD)
{
    __shared__ float th[32][33], tl[32][33];
    const int z = blockIdx.z;
    sh += (long)z * sS; sl += (long)z * sS;
    dh += (long)z * sD; dl += (long)z * sD;
    const int r0 = blockIdx.x * 32, c0 = blockIdx.y * 32;
    const int tx = threadIdx.x, ty = threadIdx.y;
#pragma unroll
    for (int i = 0; i < 4; i++) {
        const long s = (long)(r0 + ty + 8 * i) * lds + c0 + tx;
        th[ty + 8 * i][tx] = __bfloat162float(sh[s]);
        tl[ty + 8 * i][tx] = __bfloat162float(sl[s]);
    }
    __syncthreads();
#pragma unroll
    for (int i = 0; i < 4; i++) {
        const long d = (long)(c0 + ty + 8 * i) * ldd + r0 + tx;
        dh[d] = __float2bfloat16_rn(th[tx][ty + 8 * i]);
        dl[d] = __float2bfloat16_rn(tl[tx][ty + 8 * i]);
    }
}

// --------------------------- rmsnorm: f32 -> split --------------------------
__global__ void __launch_bounds__(256)
rmsnorm_qa_kernel(const float* __restrict__ w)
{
    const long row = blockIdx.x;
    const float* p = g_qa_f + row * Q_LORA;
    const int tid = threadIdx.x;
    float v[6];
    float ss = 0.f;
#pragma unroll
    for (int i = 0; i < 6; i++) { v[i] = p[tid + i * 256]; ss += v[i] * v[i]; }
    __shared__ float red[256];
    red[tid] = ss; __syncthreads();
    for (int o = 128; o > 0; o >>= 1) {
        if (tid < o) red[tid] += red[tid + o];
        __syncthreads();
    }
    const float scale = rsqrtf(red[0] / (float)Q_LORA + EPS_F);
#pragma unroll
    for (int i = 0; i < 6; i++) {
        const int c = tid + i * 256;
        bf16 h, l;
        bsplit(v[i] * scale * w[c], h, l);
        g_qah[row * Q_LORA + c] = h;
        g_qal[row * Q_LORA + c] = l;
    }
}

// ------------- kv_process: f32 kv -> split kf (norm + rope) -----------------
__global__ void __launch_bounds__(256)
kv_process_kernel(const float* __restrict__ kv_norm_w,
                  const float* __restrict__ fcos,
                  const float* __restrict__ fsin)
{
    const long row = blockIdx.x;
    const int pos = (int)(row & (SEQ - 1));
    const float* src = g_kv_f + row * QKD;
    const int tid = threadIdx.x;

    const float v0 = src[tid], v1 = src[tid + 256];
    __shared__ float red[256];
    red[tid] = v0 * v0 + v1 * v1; __syncthreads();
    for (int o = 128; o > 0; o >>= 1) {
        if (tid < o) red[tid] += red[tid + o];
        __syncthreads();
    }
    const float scale = rsqrtf(red[0] / (float)KV_LORA + EPS_F);
    bf16 h, l;
    bsplit(v0 * scale * kv_norm_w[tid], h, l);
    g_kfh[row * QKD + tid] = h; g_kfl[row * QKD + tid] = l;
    bsplit(v1 * scale * kv_norm_w[tid + 256], h, l);
    g_kfh[row * QKD + tid + 256] = h; g_kfl[row * QKD + tid + 256] = l;

    if (tid < 32) {
        const float x0 = src[KV_LORA + 2 * tid];
        const float x1 = src[KV_LORA + 2 * tid + 1];
        const float c = fcos[pos * 32 + tid];
        const float s = fsin[pos * 32 + tid];
        bsplit(x0 * c - x1 * s, h, l);
        g_kfh[row * QKD + KV_LORA + 2 * tid] = h;
        g_kfl[row * QKD + KV_LORA + 2 * tid] = l;
        bsplit(x0 * s + x1 * c, h, l);
        g_kfh[row * QKD + KV_LORA + 2 * tid + 1] = h;
        g_kfl[row * QKD + KV_LORA + 2 * tid + 1] = l;
    }
}

// ------------- q rope (in place on split q, cols 128:192 per head) ----------
__global__ void __launch_bounds__(512)
q_rope_kernel(const float* __restrict__ fcos, const float* __restrict__ fsin)
{
    const long row = blockIdx.x;
    const int pos = (int)(row & (SEQ - 1));
    const int h = threadIdx.x / 32;
    const int i = threadIdx.x % 32;

    const long si = row * (N_HEADS * QK_HEAD) + h * QK_HEAD + NOPE + 2 * i;
    const float x0 = __bfloat162float(g_qh[si])     + __bfloat162float(g_ql[si]);
    const float x1 = __bfloat162float(g_qh[si + 1]) + __bfloat162float(g_ql[si + 1]);
    const float c = fcos[pos * 32 + i];
    const float s = fsin[pos * 32 + i];
    bf16 hh, ll;
    bsplit(x0 * c - x1 * s, hh, ll);
    g_qh[si] = hh; g_ql[si] = ll;
    bsplit(x0 * s + x1 * c, hh, ll);
    g_qh[si + 1] = hh; g_ql[si + 1] = ll;
}

// ------------- broadcast k_pe into k_eff cols 128:192 for all heads ---------
__global__ void __launch_bounds__(512)
kpe_fill_kernel()
{
    const long row = blockIdx.x;                 // global row = b*2048 + t
    const int b = (int)(row >> 11);
    const int t = (int)(row & (SEQ - 1));
    const long src = row * QKD + KV_LORA;
#pragma unroll
    for (int it = 0; it < 2; it++) {
        const int e = threadIdx.x + it * 512;    // 0..1023
        const int h = e >> 6, j = e & 63;
        const long dst = ((long)(b * N_HEADS + h) * SEQ + t) * QK_HEAD + NOPE + j;
        g_keh[dst] = g_kfh[src + j];
        g_kel[dst] = g_kfl[src + j];
    }
}

// ------------- softmax (causal extent only) ---------------------------------
__global__ void __launch_bounds__(256)
softmax_mask_kernel(const float* __restrict__ mask)
{
    const long row = blockIdx.x;
    const int s = (int)(row & (SEQ - 1));
    const int T = ((s >> 7) + 1) << 7;
    const float* p = g_sc + row * SEQ;
    const float* mrow = mask + (long)s * SEQ;
    const int tid = threadIdx.x;
    const int t0 = tid * 8;
    const bool act = t0 < T;

    float v[8];
    float mx = -INFINITY;
    if (act) {
        const float4 a = reinterpret_cast<const float4*>(p + t0)[0];
        const float4 b = reinterpret_cast<const float4*>(p + t0)[1];
        const float4 ma = reinterpret_cast<const float4*>(mrow + t0)[0];
        const float4 mb = reinterpret_cast<const float4*>(mrow + t0)[1];
        v[0] = a.x + ma.x; v[1] = a.y + ma.y; v[2] = a.z + ma.z; v[3] = a.w + ma.w;
        v[4] = b.x + mb.x; v[5] = b.y + mb.y; v[6] = b.z + mb.z; v[7] = b.w + mb.w;
#pragma unroll
        for (int i = 0; i < 8; i++) mx = fmaxf(mx, v[i]);
    }
    __shared__ float red[256];
    red[tid] = mx; __syncthreads();
    for (int o = 128; o > 0; o >>= 1) {
        if (tid < o) red[tid] = fmaxf(red[tid], red[tid + o]);
        __syncthreads();
    }
    mx = red[0]; __syncthreads();

    float sum = 0.f;
    if (act) {
#pragma unroll
        for (int i = 0; i < 8; i++) { v[i] = expf(v[i] - mx); sum += v[i]; }
    }
    red[tid] = sum; __syncthreads();
    for (int o = 128; o > 0; o >>= 1) {
        if (tid < o) red[tid] += red[tid + o];
        __syncthreads();
    }
    const float inv = 1.f / red[0];

    if (act) {
#pragma unroll
        for (int i = 0; i < 4; i++) {
            bf16 h0, l0, h1, l1;
            bsplit(v[2 * i] * inv, h0, l0);
            bsplit(v[2 * i + 1] * inv, h1, l1);
            reinterpret_cast<__nv_bfloat162*>(g_Ph + row * SEQ + t0)[i]
                = __nv_bfloat162(h0, h1);
            reinterpret_cast<__nv_bfloat162*>(g_Pl + row * SEQ + t0)[i]
                = __nv_bfloat162(l0, l1);
        }
    }
}

// ---------------------------------------------------------------------------
extern "C" void kernel_launch(void* const* d_in, const int* in_sizes, int n_in,
                              void* d_out, int out_size)
{
    const float* x         = (const float*)d_in[0];
    const float* fcos      = (const float*)d_in[1];
    const float* fsin      = (const float*)d_in[2];
    const float* mask      = (const float*)d_in[3];
    const float* wq_a      = (const float*)d_in[4];
    const float* q_norm_w  = (const float*)d_in[5];
    const float* wq_b      = (const float*)d_in[6];
    const float* wkv_a     = (const float*)d_in[7];
    const float* kv_norm_w = (const float*)d_in[8];
    const float* wkv_b     = (const float*)d_in[9];
    const float* wo        = (const float*)d_in[10];
    float* out = (float*)d_out;

    bf16 *xh, *xl, *wqah, *wqal, *wqbh, *wqbl, *wkvah, *wkval, *wkvbh, *wkvbl;
    bf16 *woh, *wol, *qah, *qal, *qh, *ql, *kfh, *kfl;
    bf16 *keh, *kel, *veh, *vel, *vTh, *vTl, *Ph, *Pl, *o2h, *o2l;
    float *qaf, *kvf, *sc;
    cudaGetSymbolAddress((void**)&xh, g_xh);     cudaGetSymbolAddress((void**)&xl, g_xl);
    cudaGetSymbolAddress((void**)&wqah, g_wqah); cudaGetSymbolAddress((void**)&wqal, g_wqal);
    cudaGetSymbolAddress((void**)&wqbh, g_wqbh); cudaGetSymbolAddress((void**)&wqbl, g_wqbl);
    cudaGetSymbolAddress((void**)&wkvah, g_wkvah); cudaGetSymbolAddress((void**)&wkval, g_wkval);
    cudaGetSymbolAddress((void**)&wkvbh, g_wkvbh); cudaGetSymbolAddress((void**)&wkvbl, g_wkvbl);
    cudaGetSymbolAddress((void**)&woh, g_woh);   cudaGetSymbolAddress((void**)&wol, g_wol);
    cudaGetSymbolAddress((void**)&qaf, g_qa_f);
    cudaGetSymbolAddress((void**)&qah, g_qah);   cudaGetSymbolAddress((void**)&qal, g_qal);
    cudaGetSymbolAddress((void**)&qh, g_qh);     cudaGetSymbolAddress((void**)&ql, g_ql);
    cudaGetSymbolAddress((void**)&kvf, g_kv_f);
    cudaGetSymbolAddress((void**)&kfh, g_kfh);   cudaGetSymbolAddress((void**)&kfl, g_kfl);
    cudaGetSymbolAddress((void**)&keh, g_keh);   cudaGetSymbolAddress((void**)&kel, g_kel);
    cudaGetSymbolAddress((void**)&veh, g_veh);   cudaGetSymbolAddress((void**)&vel, g_vel);
    cudaGetSymbolAddress((void**)&vTh, g_vTh);   cudaGetSymbolAddress((void**)&vTl, g_vTl);
    cudaGetSymbolAddress((void**)&sc, g_sc);
    cudaGetSymbolAddress((void**)&Ph, g_Ph);     cudaGetSymbolAddress((void**)&Pl, g_Pl);
    cudaGetSymbolAddress((void**)&o2h, g_o2h);   cudaGetSymbolAddress((void**)&o2l, g_o2l);

    cudaFuncSetAttribute(gemm_bf3<0>, cudaFuncAttributeMaxDynamicSharedMemorySize, SMEM_BYTES);
    cudaFuncSetAttribute(gemm_bf3<1>, cudaFuncAttributeMaxDynamicSharedMemorySize, SMEM_BYTES);

    dim3 blk(256);
    dim3 tb(32, 8);

    // 0. split inputs + weights
    auto splits = [&](const float* s, bf16* h, bf16* l, long n) {
        const long n4 = n / 4;
        int gs = (int)min((n4 + 255) / 256, (long)4096);
        split_kernel<<<gs, blk>>>(s, h, l, n4);
    };
    splits(x,     xh,    xl,    (long)ROWS * DIM);
    splits(wq_a,  wqah,  wqal,  (long)Q_LORA * DIM);
    splits(wq_b,  wqbh,  wqbl,  (long)N_HEADS * QK_HEAD * Q_LORA);
    splits(wkv_a, wkvah, wkval, (long)QKD * DIM);
    splits(wkv_b, wkvbh, wkvbl, (long)N_HEADS * 256 * KV_LORA);
    splits(wo,    woh,   wol,   (long)DIM * DIM);

    // 1. qa_f = x @ wq_a^T  (f32 out)
    gemm_bf3<0><<<dim3(ROWS/256, Q_LORA/128, 1), blk, SMEM_BYTES>>>(
        xh, xl, wqah, wqal, qaf, nullptr, nullptr,
        ROWS, Q_LORA, DIM, DIM, DIM, Q_LORA, 0,0, 0,0, 0,0, 1, 1.f, 0);

    // 2. rmsnorm -> split qa
    rmsnorm_qa_kernel<<<ROWS, blk>>>(q_norm_w);

    // 3. q = qa @ wq_b^T  (split out) [4096, 3072]
    gemm_bf3<1><<<dim3(ROWS/256, (N_HEADS*QK_HEAD)/128, 1), blk, SMEM_BYTES>>>(
        qah, qal, wqbh, wqbl, nullptr, qh, ql,
        ROWS, N_HEADS*QK_HEAD, Q_LORA, Q_LORA, Q_LORA, N_HEADS*QK_HEAD,
        0,0, 0,0, 0,0, 1, 1.f, 0);

    // 4. kv_f = x @ wkv_a^T  (f32 out) [4096, 576]
    gemm_bf3<0><<<dim3(ROWS/256, (QKD+127)/128, 1), blk, SMEM_BYTES>>>(
        xh, xl, wkvah, wkval, kvf, nullptr, nullptr,
        ROWS, QKD, DIM, DIM, DIM, QKD, 0,0, 0,0, 0,0, 1, 1.f, 0);

    // 5. kv -> split kf (rmsnorm c + rope k_pe)
    kv_process_kernel<<<ROWS, blk>>>(kv_norm_w, fcos, fsin);

    // 6. rope(q_pe) in place on split q
    q_rope_kernel<<<ROWS, 512>>>(fcos, fsin);

    // 7. k_eff[b,h][t,0:128] = kf_c[b] @ wkvb_nope[h]^T  (split out, ldc=192)
    gemm_bf3<1><<<dim3(SEQ/256, 1, NBH), blk, SMEM_BYTES>>>(
        kfh, kfl, wkvbh, wkvbl, nullptr, keh, kel,
        SEQ, NOPE, KV_LORA, QKD, KV_LORA, QK_HEAD,
        (long)SEQ*QKD, 0,
        0, (long)256*KV_LORA,
        (long)N_HEADS*SEQ*QK_HEAD, (long)SEQ*QK_HEAD,
        N_HEADS, 1.f, 0);

    // 8. broadcast k_pe into k_eff cols 128:192
    kpe_fill_kernel<<<ROWS, 512>>>();

    // 9. v_eff[b,h][t,0:128] = kf_c[b] @ wkvb_v[h]^T  (split out, ldc=128)
    gemm_bf3<1><<<dim3(SEQ/256, 1, NBH), blk, SMEM_BYTES>>>(
        kfh, kfl, wkvbh + (size_t)NOPE*KV_LORA, wkvbl + (size_t)NOPE*KV_LORA,
        nullptr, veh, vel,
        SEQ, V_HEAD, KV_LORA, QKD, KV_LORA, V_HEAD,
        (long)SEQ*QKD, 0,
        0, (long)256*KV_LORA,
        (long)N_HEADS*SEQ*V_HEAD, (long)SEQ*V_HEAD,
        N_HEADS, 1.f, 0);

    // 10. transpose v_eff -> v_effT [b,h][128][t]
    transpose_bf2<<<dim3(SEQ/32, V_HEAD/32, NBH), tb>>>(
        veh, vel, vTh, vTl, V_HEAD, SEQ,
        (long)SEQ*V_HEAD, (long)V_HEAD*SEQ);

    // 11. scores = SCALE * q' @ k_eff^T  (K=192, causal tiles only)
    gemm_bf3<0><<<dim3(SEQ/256, SEQ/128, NBH), blk, SMEM_BYTES>>>(
        qh, ql, keh, kel, sc, nullptr, nullptr,
        SEQ, SEQ, QK_HEAD, N_HEADS*QK_HEAD, QK_HEAD, SEQ,
        (long)SEQ*N_HEADS*QK_HEAD, QK_HEAD,
        (long)N_HEADS*SEQ*QK_HEAD, (long)SEQ*QK_HEAD,
        (long)N_HEADS*SEQ*SEQ, (long)SEQ*SEQ,
        N_HEADS, SCALE_F, 1);

    // 12. softmax -> split P (causal extent)
    softmax_mask_kernel<<<NBH*SEQ, blk>>>(mask);

    // 13. o2[b*2048+s, h*128:..] = P[b,h] @ v_effT[b,h]^T  (causal K bound)
    gemm_bf3<1><<<dim3(SEQ/256, 1, NBH), blk, SMEM_BYTES>>>(
        Ph, Pl, vTh, vTl, nullptr, o2h, o2l,
        SEQ, V_HEAD, SEQ, SEQ, SEQ, DIM,
        (long)N_HEADS*SEQ*SEQ, (long)SEQ*SEQ,
        (long)N_HEADS*V_HEAD*SEQ, (long)V_HEAD*SEQ,
        (long)SEQ*DIM, V_HEAD,
        N_HEADS, 1.f, 2);

    // 14. out = o2 @ wo^T  (f32 out)
    gemm_bf3<0><<<dim3(ROWS/256, DIM/128, 1), blk, SMEM_BYTES>>>(
        o2h, o2l, woh, wol, out, nullptr, nullptr,
        ROWS, DIM, DIM, DIM, DIM, DIM, 0,0, 0,0, 0,0, 1, 1.f, 0);
}

// round 11
// speedup vs baseline: 1.7351x; 1.0797x over previous
#include <cuda_runtime.h>
#include <cuda_bf16.h>
#include <math.h>
#include <stdint.h>

// ---------------------------------------------------------------------------
// MLA forward. Split-bf16 3-term tensor-core GEMMs (Ah.Bh + Ah.Bl + Al.Bh).
// Round 11: wave-tail + traffic trims.
//  - qa+kv projections merged into ONE GEMM (combined 2112-row weight).
//  - k_eff+v_eff merged into ONE GEMM into unified [t][320] buffer
//    (k_nope | k_pe | v) via epilogue column shift.
//  - softmax applies causal mask inline (no 270MB mask read; exact).
// De-absorbed attention + causal block skipping from round 10 retained.
// PTX-stable on compute_103 (no tcgen05).
// ---------------------------------------------------------------------------

#define DIM     2048
#define N_HEADS 16
#define Q_LORA  1536
#define KV_LORA 512
#define NOPE    128
#define ROPE    64
#define V_HEAD  128
#define QK_HEAD 192
#define BATCH   2
#define SEQ     2048
#define ROWS    (BATCH * SEQ)
#define QKD     (KV_LORA + ROPE)        // 576
#define NBH     (BATCH * N_HEADS)       // 32
#define NCOMB   (Q_LORA + QKD)          // 2112 (merged qa+kv output width)
#define KVW     320                     // unified k/v row: 128 nope + 64 rope + 128 v
#define SCALE_F 0.0721687836487032f
#define EPS_F   1e-6f

typedef __nv_bfloat16 bf16;

// ------------------------- scratch (device globals) -------------------------
__device__ __align__(256) bf16  g_xh    [(size_t)ROWS * DIM];
__device__ __align__(256) bf16  g_xl    [(size_t)ROWS * DIM];
__device__ __align__(256) bf16  g_wcombh[(size_t)NCOMB * DIM];   // [wq_a ; wkv_a]
__device__ __align__(256) bf16  g_wcombl[(size_t)NCOMB * DIM];
__device__ __align__(256) bf16  g_wqbh  [(size_t)N_HEADS * QK_HEAD * Q_LORA];
__device__ __align__(256) bf16  g_wqbl  [(size_t)N_HEADS * QK_HEAD * Q_LORA];
__device__ __align__(256) bf16  g_wkvbh [(size_t)N_HEADS * 256 * KV_LORA];
__device__ __align__(256) bf16  g_wkvbl [(size_t)N_HEADS * 256 * KV_LORA];
__device__ __align__(256) bf16  g_woh   [(size_t)DIM * DIM];
__device__ __align__(256) bf16  g_wol   [(size_t)DIM * DIM];

__device__ __align__(256) float g_qakv_f[(size_t)ROWS * NCOMB];  // qa | kv
__device__ __align__(256) bf16  g_qah   [(size_t)ROWS * Q_LORA];
__device__ __align__(256) bf16  g_qal   [(size_t)ROWS * Q_LORA];
__device__ __align__(256) bf16  g_qh    [(size_t)ROWS * N_HEADS * QK_HEAD];
__device__ __align__(256) bf16  g_ql    [(size_t)ROWS * N_HEADS * QK_HEAD];
__device__ __align__(256) bf16  g_kfh   [(size_t)ROWS * QKD];
__device__ __align__(256) bf16  g_kfl   [(size_t)ROWS * QKD];

__device__ __align__(256) bf16  g_kveh  [(size_t)NBH * SEQ * KVW]; // [b,h][t][320]
__device__ __align__(256) bf16  g_kvel  [(size_t)NBH * SEQ * KVW];
__device__ __align__(256) bf16  g_vTh   [(size_t)NBH * V_HEAD * SEQ];
__device__ __align__(256) bf16  g_vTl   [(size_t)NBH * V_HEAD * SEQ];

__device__ __align__(256) float g_sc    [(size_t)NBH * SEQ * SEQ];
__device__ __align__(256) bf16  g_Ph    [(size_t)NBH * SEQ * SEQ];
__device__ __align__(256) bf16  g_Pl    [(size_t)NBH * SEQ * SEQ];
__device__ __align__(256) bf16  g_o2h   [(size_t)ROWS * DIM];
__device__ __align__(256) bf16  g_o2l   [(size_t)ROWS * DIM];

// ----------------------------- helpers --------------------------------------
__device__ __forceinline__ uint32_t smem_u32(const void* p) {
    uint32_t a;
    asm("{ .reg .u64 t; cvta.to.shared.u64 t, %1; cvt.u32.u64 %0, t; }"
        : "=r"(a) : "l"(p));
    return a;
}
__device__ __forceinline__ void cp16(uint32_t dst, const void* src) {
    asm volatile("cp.async.ca.shared.global [%0], [%1], 16;"
                 :: "r"(dst), "l"(src) : "memory");
}
#define CP_COMMIT() asm volatile("cp.async.commit_group;" ::: "memory")
#define CP_WAIT(n)  asm volatile("cp.async.wait_group %0;" :: "n"(n) : "memory")

__device__ __forceinline__ void ldm_x4(uint32_t* r, uint32_t addr) {
    asm volatile("ldmatrix.sync.aligned.m8n8.x4.shared.b16 {%0,%1,%2,%3}, [%4];"
                 : "=r"(r[0]), "=r"(r[1]), "=r"(r[2]), "=r"(r[3]) : "r"(addr));
}
__device__ __forceinline__ void mma_bf16(float* d, const uint32_t* a,
                                         const uint32_t* b) {
    asm volatile(
        "mma.sync.aligned.m16n8k16.row.col.f32.bf16.bf16.f32 "
        "{%0,%1,%2,%3}, {%4,%5,%6,%7}, {%8,%9}, {%0,%1,%2,%3};"
        : "+f"(d[0]), "+f"(d[1]), "+f"(d[2]), "+f"(d[3])
        : "r"(a[0]), "r"(a[1]), "r"(a[2]), "r"(a[3]), "r"(b[0]), "r"(b[1]));
}
__device__ __forceinline__ void bsplit(float x, bf16& h, bf16& l) {
    h = __float2bfloat16_rn(x);
    l = __float2bfloat16_rn(x - __bfloat162float(h));
}

// ----------------------- GEMM: C = alpha * A.B^T ----------------------------
// CTA tile 256x128, BK=32, 256 threads, warp tile 64x64 (4m x 2n warps).
// A,B pre-split bf16 hi/lo, K-major. M%256==0, K%32==0, N arbitrary.
// OUTM=0: C f32.  OUTM=1: C split to Ch/Cl bf16.
// mode bit0: skip tiles with n0 > m0+128 (causal scores)
// mode bit1: limit K to m0+256          (causal P.V)
// mode bit2: output col += 64 when col >= 128 (unified k/v layout)
#define ROWB 80
#define AT_B (256 * ROWB)
#define BT_B (128 * ROWB)
#define STG_B (2 * AT_B + 2 * BT_B)      // 61440
#define SMEM_BYTES (2 * STG_B)           // 122880

__device__ __forceinline__ void load_tileA(uint32_t dst, const bf16* __restrict__ src,
                                           int ld, int k0, int tid) {
#pragma unroll
    for (int it = 0; it < 4; it++) {
        const int idx = tid + it * 256;
        const int row = idx >> 2, seg = idx & 3;
        cp16(dst + (uint32_t)(row * ROWB + seg * 16),
             src + (size_t)row * ld + k0 + seg * 8);
    }
}
__device__ __forceinline__ void load_tileB(uint32_t dst, const bf16* __restrict__ src,
                                           int ld, int k0, int limit, int tid) {
#pragma unroll
    for (int it = 0; it < 2; it++) {
        const int idx = tid + it * 256;
        const int row = idx >> 2, seg = idx & 3;
        const uint32_t d = dst + (uint32_t)(row * ROWB + seg * 16);
        if (row < limit) {
            cp16(d, src + (size_t)row * ld + k0 + seg * 8);
        } else {
            asm volatile("st.shared.v4.b32 [%0], {%1,%1,%1,%1};"
                         :: "r"(d), "r"(0) : "memory");
        }
    }
}
__device__ __forceinline__ void load_stage(uint32_t base,
                                           const bf16* Ath, const bf16* Atl,
                                           const bf16* Bth, const bf16* Btl,
                                           int lda, int ldb, int k0, int nlim, int tid) {
    load_tileA(base,                Ath, lda, k0, tid);
    load_tileA(base + AT_B,         Atl, lda, k0, tid);
    load_tileB(base + 2 * AT_B,        Bth, ldb, k0, nlim, tid);
    load_tileB(base + 2 * AT_B + BT_B, Btl, ldb, k0, nlim, tid);
}

template <int OUTM>
__global__ void __launch_bounds__(256)
gemm_bf3(const bf16* __restrict__ Ah, const bf16* __restrict__ Al,
         const bf16* __restrict__ Bh, const bf16* __restrict__ Bl,
         float* __restrict__ C, bf16* __restrict__ Ch, bf16* __restrict__ Cl,
         int M, int N, int K, int lda, int ldb, int ldc,
         long sAo, long sAi, long sBo, long sBi, long sCo, long sCi,
         int inner, float alpha, int mode)
{
    const int m0 = blockIdx.x * 256, n0 = blockIdx.y * 128;
    if ((mode & 1) && n0 > m0 + 128) return;

    extern __shared__ char smem[];
    const uint32_t sb = smem_u32(smem);
    const int tid = threadIdx.x, lane = tid & 31, wid = tid >> 5;
    const int wm = wid >> 1, wn = wid & 1;
    const int g = lane >> 2, tig = lane & 3;

    const int z = blockIdx.z, zo = z / inner, zi = z - zo * inner;
    const long ofA = (long)zo * sAo + (long)zi * sAi;
    const long ofB = (long)zo * sBo + (long)zi * sBi;
    const long ofC = (long)zo * sCo + (long)zi * sCi;
    Ah += ofA; Al += ofA;
    Bh += ofB; Bl += ofB;

    const bf16* Ath = Ah + (size_t)m0 * lda;
    const bf16* Atl = Al + (size_t)m0 * lda;
    const bf16* Bth = Bh + (size_t)n0 * ldb;
    const bf16* Btl = Bl + (size_t)n0 * ldb;
    const int nlim = min(128, N - n0);

    float acc[4][8][4];
#pragma unroll
    for (int i = 0; i < 4; i++)
#pragma unroll
        for (int j = 0; j < 8; j++)
#pragma unroll
            for (int r = 0; r < 4; r++) acc[i][j][r] = 0.f;

    const int Keff = (mode & 2) ? min(K, m0 + 256) : K;
    const int nch = Keff >> 5;

    load_stage(sb, Ath, Atl, Bth, Btl, lda, ldb, 0, nlim, tid);
    CP_COMMIT();

    const uint32_t aoffL = (uint32_t)((wm * 64 + (lane & 15)) * ROWB + (lane >> 4) * 16);
    const uint32_t boffL = (uint32_t)((wn * 64 + ((lane >> 4) & 1) * 8 + (lane & 7)) * ROWB
                                      + ((lane >> 3) & 1) * 16);

    for (int c = 0; c < nch; c++) {
        if (c + 1 < nch) {
            load_stage(sb + ((c + 1) & 1) * STG_B, Ath, Atl, Bth, Btl,
                       lda, ldb, (c + 1) << 5, nlim, tid);
            CP_COMMIT();
            CP_WAIT(1);
        } else {
            CP_WAIT(0);
        }
        __syncthreads();

        const uint32_t base = sb + (c & 1) * STG_B;
        const uint32_t aA = base + aoffL;
        const uint32_t bA = base + 2 * AT_B + boffL;

#pragma unroll
        for (int ks = 0; ks < 2; ks++) {
            uint32_t bh[4][4], bl[4][4];
#pragma unroll
            for (int jj = 0; jj < 4; jj++) {
                ldm_x4(bh[jj], bA + ks * 32 + jj * 16 * ROWB);
                ldm_x4(bl[jj], bA + BT_B + ks * 32 + jj * 16 * ROWB);
            }
#pragma unroll
            for (int i = 0; i < 4; i++) {
                uint32_t ahf[4], alf[4];
                ldm_x4(ahf, aA + ks * 32 + i * 16 * ROWB);
                ldm_x4(alf, aA + AT_B + ks * 32 + i * 16 * ROWB);
#pragma unroll
                for (int j = 0; j < 8; j++) {
                    const uint32_t* bhp = &bh[j >> 1][(j & 1) * 2];
                    const uint32_t* blp = &bl[j >> 1][(j & 1) * 2];
                    mma_bf16(acc[i][j], alf, bhp);
                    mma_bf16(acc[i][j], ahf, blp);
                    mma_bf16(acc[i][j], ahf, bhp);
                }
            }
        }
        __syncthreads();
    }

    // epilogue
#pragma unroll
    for (int i = 0; i < 4; i++) {
        const int r0 = m0 + wm * 64 + i * 16 + g;
#pragma unroll
        for (int j = 0; j < 8; j++) {
            const int col = n0 + wn * 64 + j * 8 + tig * 2;
            if (col >= N) continue;
            const int ocol = ((mode & 4) && col >= 128) ? col + 64 : col;
            const float c0 = alpha * acc[i][j][0], c1 = alpha * acc[i][j][1];
            const float c2 = alpha * acc[i][j][2], c3 = alpha * acc[i][j][3];
            if (OUTM == 0) {
                float* p0 = C + ofC + (size_t)r0 * ldc + ocol;
                float* p1 = C + ofC + (size_t)(r0 + 8) * ldc + ocol;
                if (col + 1 < N) {
                    *reinterpret_cast<float2*>(p0) = make_float2(c0, c1);
                    *reinterpret_cast<float2*>(p1) = make_float2(c2, c3);
                } else { p0[0] = c0; p1[0] = c2; }
            } else {
                bf16 h0, l0, h1, l1, h2, l2, h3, l3;
                bsplit(c0, h0, l0); bsplit(c1, h1, l1);
                bsplit(c2, h2, l2); bsplit(c3, h3, l3);
                *reinterpret_cast<__nv_bfloat162*>(Ch + ofC + (size_t)r0 * ldc + ocol)
                    = __nv_bfloat162(h0, h1);
                *reinterpret_cast<__nv_bfloat162*>(Cl + ofC + (size_t)r0 * ldc + ocol)
                    = __nv_bfloat162(l0, l1);
                *reinterpret_cast<__nv_bfloat162*>(Ch + ofC + (size_t)(r0 + 8) * ldc + ocol)
                    = __nv_bfloat162(h2, h3);
                *reinterpret_cast<__nv_bfloat162*>(Cl + ofC + (size_t)(r0 + 8) * ldc + ocol)
                    = __nv_bfloat162(l2, l3);
            }
        }
    }
}

// ---------------------- elementwise split f32 -> bf16 hi/lo ------------------
__global__ void __launch_bounds__(256)
split_kernel(const float* __restrict__ src, bf16* __restrict__ h,
             bf16* __restrict__ l, long n4)
{
    const long stride = (long)gridDim.x * blockDim.x;
    for (long i = blockIdx.x * (long)blockDim.x + threadIdx.x; i < n4; i += stride) {
        const float4 v = reinterpret_cast<const float4*>(src)[i];
        bf16 h0, l0, h1, l1, h2, l2, h3, l3;
        bsplit(v.x, h0, l0); bsplit(v.y, h1, l1);
        bsplit(v.z, h2, l2); bsplit(v.w, h3, l3);
        reinterpret_cast<__nv_bfloat162*>(h)[i * 2]     = __nv_bfloat162(h0, h1);
        reinterpret_cast<__nv_bfloat162*>(h)[i * 2 + 1] = __nv_bfloat162(h2, h3);
        reinterpret_cast<__nv_bfloat162*>(l)[i * 2]     = __nv_bfloat162(l0, l1);
        reinterpret_cast<__nv_bfloat162*>(l)[i * 2 + 1] = __nv_bfloat162(l2, l3);
    }
}

// ------------------- dual bf16 transpose (32x32 tiles) ----------------------
__global__ void __launch_bounds__(256)
transpose_bf2(const bf16* __restrict__ sh, const bf16* __restrict__ sl,
              bf16* __restrict__ dh, bf16* __restrict__ dl,
              int lds, int ldd, long sS, long sD)
{
    __shared__ float th[32][33], tl[32][33];
    const int z = blockIdx.z;
    sh += (long)z * sS; sl += (long)z * sS;
    dh += (long)z * sD; dl += (long)z * sD;
    const int r0 = blockIdx.x * 32, c0 = blockIdx.y * 32;
    const int tx = threadIdx.x, ty = threadIdx.y;
#pragma unroll
    for (int i = 0; i < 4; i++) {
        const long s = (long)(r0 + ty + 8 * i) * lds + c0 + tx;
        th[ty + 8 * i][tx] = __bfloat162float(sh[s]);
        tl[ty + 8 * i][tx] = __bfloat162float(sl[s]);
    }
    __syncthreads();
#pragma unroll
    for (int i = 0; i < 4; i++) {
        const long d = (long)(c0 + ty + 8 * i) * ldd + r0 + tx;
        dh[d] = __float2bfloat16_rn(th[tx][ty + 8 * i]);
        dl[d] = __float2bfloat16_rn(tl[tx][ty + 8 * i]);
    }
}

// --------------------------- rmsnorm: f32 -> split --------------------------
__global__ void __launch_bounds__(256)
rmsnorm_qa_kernel(const float* __restrict__ w)
{
    const long row = blockIdx.x;
    const float* p = g_qakv_f + row * NCOMB;
    const int tid = threadIdx.x;
    float v[6];
    float ss = 0.f;
#pragma unroll
    for (int i = 0; i < 6; i++) { v[i] = p[tid + i * 256]; ss += v[i] * v[i]; }
    __shared__ float red[256];
    red[tid] = ss; __syncthreads();
    for (int o = 128; o > 0; o >>= 1) {
        if (tid < o) red[tid] += red[tid + o];
        __syncthreads();
    }
    const float scale = rsqrtf(red[0] / (float)Q_LORA + EPS_F);
#pragma unroll
    for (int i = 0; i < 6; i++) {
        const int c = tid + i * 256;
        bf16 h, l;
        bsplit(v[i] * scale * w[c], h, l);
        g_qah[row * Q_LORA + c] = h;
        g_qal[row * Q_LORA + c] = l;
    }
}

// ------------- kv_process: qakv cols 1536:2112 -> split kf ------------------
__global__ void __launch_bounds__(256)
kv_process_kernel(const float* __restrict__ kv_norm_w,
                  const float* __restrict__ fcos,
                  const float* __restrict__ fsin)
{
    const long row = blockIdx.x;
    const int pos = (int)(row & (SEQ - 1));
    const float* src = g_qakv_f + row * NCOMB + Q_LORA;
    const int tid = threadIdx.x;

    const float v0 = src[tid], v1 = src[tid + 256];
    __shared__ float red[256];
    red[tid] = v0 * v0 + v1 * v1; __syncthreads();
    for (int o = 128; o > 0; o >>= 1) {
        if (tid < o) red[tid] += red[tid + o];
        __syncthreads();
    }
    const float scale = rsqrtf(red[0] / (float)KV_LORA + EPS_F);
    bf16 h, l;
    bsplit(v0 * scale * kv_norm_w[tid], h, l);
    g_kfh[row * QKD + tid] = h; g_kfl[row * QKD + tid] = l;
    bsplit(v1 * scale * kv_norm_w[tid + 256], h, l);
    g_kfh[row * QKD + tid + 256] = h; g_kfl[row * QKD + tid + 256] = l;

    if (tid < 32) {
        const float x0 = src[KV_LORA + 2 * tid];
        const float x1 = src[KV_LORA + 2 * tid + 1];
        const float c = fcos[pos * 32 + tid];
        const float s = fsin[pos * 32 + tid];
        bsplit(x0 * c - x1 * s, h, l);
        g_kfh[row * QKD + KV_LORA + 2 * tid] = h;
        g_kfl[row * QKD + KV_LORA + 2 * tid] = l;
        bsplit(x0 * s + x1 * c, h, l);
        g_kfh[row * QKD + KV_LORA + 2 * tid + 1] = h;
        g_kfl[row * QKD + KV_LORA + 2 * tid + 1] = l;
    }
}

// ------------- q rope (in place on split q, cols 128:192 per head) ----------
__global__ void __launch_bounds__(512)
q_rope_kernel(const float* __restrict__ fcos, const float* __restrict__ fsin)
{
    const long row = blockIdx.x;
    const int pos = (int)(row & (SEQ - 1));
    const int h = threadIdx.x / 32;
    const int i = threadIdx.x % 32;

    const long si = row * (N_HEADS * QK_HEAD) + h * QK_HEAD + NOPE + 2 * i;
    const float x0 = __bfloat162float(g_qh[si])     + __bfloat162float(g_ql[si]);
    const float x1 = __bfloat162float(g_qh[si + 1]) + __bfloat162float(g_ql[si + 1]);
    const float c = fcos[pos * 32 + i];
    const float s = fsin[pos * 32 + i];
    bf16 hh, ll;
    bsplit(x0 * c - x1 * s, hh, ll);
    g_qh[si] = hh; g_ql[si] = ll;
    bsplit(x0 * s + x1 * c, hh, ll);
    g_qh[si + 1] = hh; g_ql[si + 1] = ll;
}

// ------------- broadcast k_pe into kve cols 128:192 for all heads -----------
__global__ void __launch_bounds__(512)
kpe_fill_kernel()
{
    const long row = blockIdx.x;                 // global row = b*2048 + t
    const int b = (int)(row >> 11);
    const int t = (int)(row & (SEQ - 1));
    const long src = row * QKD + KV_LORA;
#pragma unroll
    for (int it = 0; it < 2; it++) {
        const int e = threadIdx.x + it * 512;    // 0..1023
        const int h = e >> 6, j = e & 63;
        const long dst = ((long)(b * N_HEADS + h) * SEQ + t) * KVW + NOPE + j;
        g_kveh[dst] = g_kfh[src + j];
        g_kvel[dst] = g_kfl[src + j];
    }
}

// ------------- softmax (causal mask inline, causal extent only) -------------
__global__ void __launch_bounds__(256)
softmax_mask_kernel()
{
    const long row = blockIdx.x;
    const int s = (int)(row & (SEQ - 1));
    const int T = ((s >> 7) + 1) << 7;
    const float* p = g_sc + row * SEQ;
    const int tid = threadIdx.x;
    const int t0 = tid * 8;
    const bool act = t0 < T;

    float v[8];
    float mx = -INFINITY;
    if (act) {
        const float4 a = reinterpret_cast<const float4*>(p + t0)[0];
        const float4 b = reinterpret_cast<const float4*>(p + t0)[1];
        v[0] = a.x; v[1] = a.y; v[2] = a.z; v[3] = a.w;
        v[4] = b.x; v[5] = b.y; v[6] = b.z; v[7] = b.w;
#pragma unroll
        for (int i = 0; i < 8; i++) {
            if (t0 + i > s) v[i] = -INFINITY;    // causal mask (exact)
            mx = fmaxf(mx, v[i]);
        }
    }
    __shared__ float red[256];
    red[tid] = mx; __syncthreads();
    for (int o = 128; o > 0; o >>= 1) {
        if (tid < o) red[tid] = fmaxf(red[tid], red[tid + o]);
        __syncthreads();
    }
    mx = red[0]; __syncthreads();

    float sum = 0.f;
    if (act) {
#pragma unroll
        for (int i = 0; i < 8; i++) { v[i] = expf(v[i] - mx); sum += v[i]; }
    }
    red[tid] = sum; __syncthreads();
    for (int o = 128; o > 0; o >>= 1) {
        if (tid < o) red[tid] += red[tid + o];
        __syncthreads();
    }
    const float inv = 1.f / red[0];

    if (act) {
#pragma unroll
        for (int i = 0; i < 4; i++) {
            bf16 h0, l0, h1, l1;
            bsplit(v[2 * i] * inv, h0, l0);
            bsplit(v[2 * i + 1] * inv, h1, l1);
            reinterpret_cast<__nv_bfloat162*>(g_Ph + row * SEQ + t0)[i]
                = __nv_bfloat162(h0, h1);
            reinterpret_cast<__nv_bfloat162*>(g_Pl + row * SEQ + t0)[i]
                = __nv_bfloat162(l0, l1);
        }
    }
}

// ---------------------------------------------------------------------------
extern "C" void kernel_launch(void* const* d_in, const int* in_sizes, int n_in,
                              void* d_out, int out_size)
{
    const float* x         = (const float*)d_in[0];
    const float* fcos      = (const float*)d_in[1];
    const float* fsin      = (const float*)d_in[2];
    // d_in[3] = mask (unused; causal mask computed inline, exact per reference)
    const float* wq_a      = (const float*)d_in[4];
    const float* q_norm_w  = (const float*)d_in[5];
    const float* wq_b      = (const float*)d_in[6];
    const float* wkv_a     = (const float*)d_in[7];
    const float* kv_norm_w = (const float*)d_in[8];
    const float* wkv_b     = (const float*)d_in[9];
    const float* wo        = (const float*)d_in[10];
    float* out = (float*)d_out;

    bf16 *xh, *xl, *wch, *wcl, *wqbh, *wqbl, *wkvbh, *wkvbl, *woh, *wol;
    bf16 *qah, *qal, *qh, *ql, *kfh, *kfl, *kveh, *kvel, *vTh, *vTl;
    bf16 *Ph, *Pl, *o2h, *o2l;
    float *qakvf, *sc;
    cudaGetSymbolAddress((void**)&xh, g_xh);       cudaGetSymbolAddress((void**)&xl, g_xl);
    cudaGetSymbolAddress((void**)&wch, g_wcombh);  cudaGetSymbolAddress((void**)&wcl, g_wcombl);
    cudaGetSymbolAddress((void**)&wqbh, g_wqbh);   cudaGetSymbolAddress((void**)&wqbl, g_wqbl);
    cudaGetSymbolAddress((void**)&wkvbh, g_wkvbh); cudaGetSymbolAddress((void**)&wkvbl, g_wkvbl);
    cudaGetSymbolAddress((void**)&woh, g_woh);     cudaGetSymbolAddress((void**)&wol, g_wol);
    cudaGetSymbolAddress((void**)&qakvf, g_qakv_f);
    cudaGetSymbolAddress((void**)&qah, g_qah);     cudaGetSymbolAddress((void**)&qal, g_qal);
    cudaGetSymbolAddress((void**)&qh, g_qh);       cudaGetSymbolAddress((void**)&ql, g_ql);
    cudaGetSymbolAddress((void**)&kfh, g_kfh);     cudaGetSymbolAddress((void**)&kfl, g_kfl);
    cudaGetSymbolAddress((void**)&kveh, g_kveh);   cudaGetSymbolAddress((void**)&kvel, g_kvel);
    cudaGetSymbolAddress((void**)&vTh, g_vTh);     cudaGetSymbolAddress((void**)&vTl, g_vTl);
    cudaGetSymbolAddress((void**)&sc, g_sc);
    cudaGetSymbolAddress((void**)&Ph, g_Ph);       cudaGetSymbolAddress((void**)&Pl, g_Pl);
    cudaGetSymbolAddress((void**)&o2h, g_o2h);     cudaGetSymbolAddress((void**)&o2l, g_o2l);

    cudaFuncSetAttribute(gemm_bf3<0>, cudaFuncAttributeMaxDynamicSharedMemorySize, SMEM_BYTES);
    cudaFuncSetAttribute(gemm_bf3<1>, cudaFuncAttributeMaxDynamicSharedMemorySize, SMEM_BYTES);

    dim3 blk(256);
    dim3 tb(32, 8);

    // 0. split inputs + weights (wq_a and wkv_a into one combined buffer)
    auto splits = [&](const float* s, bf16* h, bf16* l, long n) {
        const long n4 = n / 4;
        int gs = (int)min((n4 + 255) / 256, (long)4096);
        split_kernel<<<gs, blk>>>(s, h, l, n4);
    };
    splits(x,     xh,  xl,  (long)ROWS * DIM);
    splits(wq_a,  wch, wcl, (long)Q_LORA * DIM);
    splits(wkv_a, wch + (size_t)Q_LORA * DIM, wcl + (size_t)Q_LORA * DIM,
           (long)QKD * DIM);
    splits(wq_b,  wqbh, wqbl, (long)N_HEADS * QK_HEAD * Q_LORA);
    splits(wkv_b, wkvbh, wkvbl, (long)N_HEADS * 256 * KV_LORA);
    splits(wo,    woh,  wol,  (long)DIM * DIM);

    // 1. qakv = x @ [wq_a ; wkv_a]^T  (f32 out, N=2112) -- merged
    gemm_bf3<0><<<dim3(ROWS/256, (NCOMB + 127)/128, 1), blk, SMEM_BYTES>>>(
        xh, xl, wch, wcl, qakvf, nullptr, nullptr,
        ROWS, NCOMB, DIM, DIM, DIM, NCOMB, 0,0, 0,0, 0,0, 1, 1.f, 0);

    // 2. rmsnorm(qa) -> split qa ; kv -> split kf (norm + rope)
    rmsnorm_qa_kernel<<<ROWS, blk>>>(q_norm_w);
    kv_process_kernel<<<ROWS, blk>>>(kv_norm_w, fcos, fsin);

    // 3. q = qa @ wq_b^T  (split out)
    gemm_bf3<1><<<dim3(ROWS/256, (N_HEADS*QK_HEAD)/128, 1), blk, SMEM_BYTES>>>(
        qah, qal, wqbh, wqbl, nullptr, qh, ql,
        ROWS, N_HEADS*QK_HEAD, Q_LORA, Q_LORA, Q_LORA, N_HEADS*QK_HEAD,
        0,0, 0,0, 0,0, 1, 1.f, 0);

    // 4. rope(q_pe) in place
    q_rope_kernel<<<ROWS, 512>>>(fcos, fsin);

    // 5. kve[b,h][t] = kf_c[b] @ wkvb[h]^T (N=256: nope->0:128, v->192:320)
    gemm_bf3<1><<<dim3(SEQ/256, 2, NBH), blk, SMEM_BYTES>>>(
        kfh, kfl, wkvbh, wkvbl, nullptr, kveh, kvel,
        SEQ, 256, KV_LORA, QKD, KV_LORA, KVW,
        (long)SEQ*QKD, 0,
        0, (long)256*KV_LORA,
        (long)N_HEADS*SEQ*KVW, (long)SEQ*KVW,
        N_HEADS, 1.f, 4);

    // 6. broadcast k_pe into kve cols 128:192
    kpe_fill_kernel<<<ROWS, 512>>>();

    // 7. transpose v (kve cols 192:320) -> vT [b,h][128][t]
    transpose_bf2<<<dim3(SEQ/32, V_HEAD/32, NBH), tb>>>(
        kveh + 192, kvel + 192, vTh, vTl, KVW, SEQ,
        (long)SEQ*KVW, (long)V_HEAD*SEQ);

    // 8. scores = SCALE * q' @ kve[:, 0:192]^T  (K=192, causal tiles only)
    gemm_bf3<0><<<dim3(SEQ/256, SEQ/128, NBH), blk, SMEM_BYTES>>>(
        qh, ql, kveh, kvel, sc, nullptr, nullptr,
        SEQ, SEQ, QK_HEAD, N_HEADS*QK_HEAD, KVW, SEQ,
        (long)SEQ*N_HEADS*QK_HEAD, QK_HEAD,
        (long)N_HEADS*SEQ*KVW, (long)SEQ*KVW,
        (long)N_HEADS*SEQ*SEQ, (long)SEQ*SEQ,
        N_HEADS, SCALE_F, 1);

    // 9. softmax (causal inline) -> split P
    softmax_mask_kernel<<<NBH*SEQ, blk>>>();

    // 10. o2[b*2048+s, h*128:..] = P[b,h] @ vT[b,h]^T  (causal K bound)
    gemm_bf3<1><<<dim3(SEQ/256, 1, NBH), blk, SMEM_BYTES>>>(
        Ph, Pl, vTh, vTl, nullptr, o2h, o2l,
        SEQ, V_HEAD, SEQ, SEQ, SEQ, DIM,
        (long)N_HEADS*SEQ*SEQ, (long)SEQ*SEQ,
        (long)N_HEADS*V_HEAD*SEQ, (long)V_HEAD*SEQ,
        (long)SEQ*DIM, V_HEAD,
        N_HEADS, 1.f, 2);

    // 11. out = o2 @ wo^T  (f32 out)
    gemm_bf3<0><<<dim3(ROWS/256, DIM/128, 1), blk, SMEM_BYTES>>>(
        o2h, o2l, woh, wol, out, nullptr, nullptr,
        ROWS, DIM, DIM, DIM, DIM, DIM, 0,0, 0,0, 0,0, 1, 1.f, 0);
}